// round 1
// baseline (speedup 1.0000x reference)
#include <cuda_runtime.h>
#include <math.h>

// ---------------------------------------------------------------------------
// Problem constants
// ---------------------------------------------------------------------------
static constexpr int TOK = 65536;   // B*M*P = 32*8*256
static constexpr int Dm  = 512;     // model dim
static constexpr int HA  = 256;     // H*A = 4*64

// ---------------------------------------------------------------------------
// Scratch (device globals; no runtime allocation allowed)
// ---------------------------------------------------------------------------
__device__ float g_q [TOK * HA];
__device__ float g_k [TOK * HA];
__device__ float g_v [TOK * HA];
__device__ float g_z [TOK * HA];
__device__ float g_t [TOK * Dm];    // GEMM temp (reused 3x)
__device__ float g_z2[TOK * Dm];
__device__ float g_o1[TOK * Dm];

__device__ __forceinline__ float warp_sum(float v) {
#pragma unroll
    for (int o = 16; o > 0; o >>= 1) v += __shfl_xor_sync(0xffffffffu, v, o);
    return v;
}

// ---------------------------------------------------------------------------
// Generic tiled SGEMM:  C[M,N] = A[M,K] @ W[N,K]^T + bias[N]
// BM=BN=128, BK=8, 256 threads, 8x8 register tile per thread.
// SHIFT: remap A row p -> (p+2) mod 256 within each (b,m) chunk (cyclic shift)
// ---------------------------------------------------------------------------
template<bool SHIFT>
__global__ __launch_bounds__(256) void gemm_kernel(
    const float* __restrict__ A, const float* __restrict__ W,
    const float* __restrict__ bias, float* __restrict__ C,
    int M, int N, int K)
{
    __shared__ float As[8][128];
    __shared__ float Bs[8][128];

    const int tid  = threadIdx.x;
    const int brow = blockIdx.y * 128;
    const int bcol = blockIdx.x * 128;

    const int ld_row = tid >> 1;          // 0..127
    const int ld_col = (tid & 1) * 4;     // 0 or 4

    int a_grow = brow + ld_row;
    if (SHIFT) {
        int p = a_grow & 255;
        a_grow = (a_grow & ~255) | ((p + 2) & 255);
    }
    const float* a_ptr = A + (size_t)a_grow * K + ld_col;
    const float* b_ptr = W + (size_t)(bcol + ld_row) * K + ld_col;

    const int ty = tid >> 4;   // 0..15
    const int tx = tid & 15;   // 0..15

    float acc[8][8];
#pragma unroll
    for (int i = 0; i < 8; i++)
#pragma unroll
        for (int j = 0; j < 8; j++) acc[i][j] = 0.f;

    for (int k0 = 0; k0 < K; k0 += 8) {
        float4 av = *(const float4*)(a_ptr + k0);
        float4 bv = *(const float4*)(b_ptr + k0);
        __syncthreads();
        As[ld_col + 0][ld_row] = av.x;
        As[ld_col + 1][ld_row] = av.y;
        As[ld_col + 2][ld_row] = av.z;
        As[ld_col + 3][ld_row] = av.w;
        Bs[ld_col + 0][ld_row] = bv.x;
        Bs[ld_col + 1][ld_row] = bv.y;
        Bs[ld_col + 2][ld_row] = bv.z;
        Bs[ld_col + 3][ld_row] = bv.w;
        __syncthreads();
#pragma unroll
        for (int kk = 0; kk < 8; kk++) {
            float4 ra0 = *(const float4*)&As[kk][ty * 8];
            float4 ra1 = *(const float4*)&As[kk][ty * 8 + 4];
            float4 rb0 = *(const float4*)&Bs[kk][tx * 8];
            float4 rb1 = *(const float4*)&Bs[kk][tx * 8 + 4];
            float ra[8] = {ra0.x, ra0.y, ra0.z, ra0.w, ra1.x, ra1.y, ra1.z, ra1.w};
            float rb[8] = {rb0.x, rb0.y, rb0.z, rb0.w, rb1.x, rb1.y, rb1.z, rb1.w};
#pragma unroll
            for (int i = 0; i < 8; i++)
#pragma unroll
                for (int j = 0; j < 8; j++)
                    acc[i][j] = fmaf(ra[i], rb[j], acc[i][j]);
        }
    }

#pragma unroll
    for (int i = 0; i < 8; i++) {
        const int r = brow + ty * 8 + i;
        float* crow = C + (size_t)r * N + bcol + tx * 8;
#pragma unroll
        for (int j = 0; j < 8; j += 4) {
            float4 o;
            o.x = acc[i][j + 0] + bias[bcol + tx * 8 + j + 0];
            o.y = acc[i][j + 1] + bias[bcol + tx * 8 + j + 1];
            o.z = acc[i][j + 2] + bias[bcol + tx * 8 + j + 2];
            o.w = acc[i][j + 3] + bias[bcol + tx * 8 + j + 3];
            *(float4*)(crow + j) = o;
        }
    }
}

// ---------------------------------------------------------------------------
// Windowed attention. One block per window (16384), one warp per head (H=4).
// Window size WS=4, head dim A=64 -> each lane holds 2 elems/row of q,k,v.
// Mask: only window index 63 within each (b,m); -100 between groups {0,1},{2,3}.
// ---------------------------------------------------------------------------
__global__ __launch_bounds__(128) void attn_kernel(
    const float* __restrict__ q, const float* __restrict__ k,
    const float* __restrict__ v, float* __restrict__ z)
{
    const int win  = blockIdx.x;      // 0..16383 (tokens win*4 .. win*4+3)
    const int h    = threadIdx.x >> 5;
    const int lane = threadIdx.x & 31;
    const int t0   = win * 4;
    const int col  = h * 64 + lane;   // first of two elems; second at +32

    float qr[4][2], kr[4][2], vr[4][2];
#pragma unroll
    for (int i = 0; i < 4; i++) {
        const size_t off = (size_t)(t0 + i) * HA + col;
        qr[i][0] = q[off]; qr[i][1] = q[off + 32];
        kr[i][0] = k[off]; kr[i][1] = k[off + 32];
        vr[i][0] = v[off]; vr[i][1] = v[off + 32];
    }

    float S[4][4];
#pragma unroll
    for (int i = 0; i < 4; i++)
#pragma unroll
        for (int j = 0; j < 4; j++) {
            float p = qr[i][0] * kr[j][0] + qr[i][1] * kr[j][1];
            S[i][j] = warp_sum(p) * 0.125f;   // 1/sqrt(64)
        }

    if ((win & 63) == 63) {
#pragma unroll
        for (int i = 0; i < 4; i++)
#pragma unroll
            for (int j = 0; j < 4; j++)
                if ((i < 2) != (j < 2)) S[i][j] -= 100.0f;
    }

#pragma unroll
    for (int i = 0; i < 4; i++) {
        float m = fmaxf(fmaxf(S[i][0], S[i][1]), fmaxf(S[i][2], S[i][3]));
        float e0 = expf(S[i][0] - m), e1 = expf(S[i][1] - m);
        float e2 = expf(S[i][2] - m), e3 = expf(S[i][3] - m);
        float inv = 1.f / (e0 + e1 + e2 + e3);
        S[i][0] = e0 * inv; S[i][1] = e1 * inv;
        S[i][2] = e2 * inv; S[i][3] = e3 * inv;
    }

#pragma unroll
    for (int i = 0; i < 4; i++) {
        float z0 = S[i][0] * vr[0][0] + S[i][1] * vr[1][0] + S[i][2] * vr[2][0] + S[i][3] * vr[3][0];
        float z1 = S[i][0] * vr[0][1] + S[i][1] * vr[1][1] + S[i][2] * vr[2][1] + S[i][3] * vr[3][1];
        const size_t off = (size_t)(t0 + i) * HA + col;
        z[off]      = z0;
        z[off + 32] = z1;
    }
}

// ---------------------------------------------------------------------------
// LayerNorm helpers (row = 512 floats, 128 threads, float4 per thread)
// ---------------------------------------------------------------------------
__device__ __forceinline__ void block_stats_512(float s, float ss, float& mean, float& inv) {
    __shared__ float sh[8];
    const int lane = threadIdx.x & 31, wid = threadIdx.x >> 5;
    s  = warp_sum(s);
    ss = warp_sum(ss);
    if (lane == 0) { sh[wid] = s; sh[4 + wid] = ss; }
    __syncthreads();
    float st  = sh[0] + sh[1] + sh[2] + sh[3];
    float sst = sh[4] + sh[5] + sh[6] + sh[7];
    mean = st * (1.f / 512.f);
    float var = sst * (1.f / 512.f) - mean * mean;
    inv = rsqrtf(var + 1e-5f);
}

// z2[r] = relu( x[r] + LN(t[(p-2) mod 256 row]) * g + b )   (reverse cyclic shift)
__global__ __launch_bounds__(128) void ln_shift_res_kernel(
    const float* __restrict__ t, const float* __restrict__ x,
    const float* __restrict__ g, const float* __restrict__ b,
    float* __restrict__ out)
{
    const int r   = blockIdx.x;
    const int tid = threadIdx.x;
    const int p   = r & 255;
    const int src = (r & ~255) | ((p + 254) & 255);   // (p-2) mod 256

    float4 v = ((const float4*)(t + (size_t)src * Dm))[tid];
    float s  = v.x + v.y + v.z + v.w;
    float ss = v.x * v.x + v.y * v.y + v.z * v.z + v.w * v.w;
    float mean, inv;
    block_stats_512(s, ss, mean, inv);

    float4 xv = ((const float4*)(x + (size_t)r * Dm))[tid];
    float4 gv = ((const float4*)g)[tid];
    float4 bv = ((const float4*)b)[tid];
    float4 o;
    o.x = fmaxf(0.f, xv.x + (v.x - mean) * inv * gv.x + bv.x);
    o.y = fmaxf(0.f, xv.y + (v.y - mean) * inv * gv.y + bv.y);
    o.z = fmaxf(0.f, xv.z + (v.z - mean) * inv * gv.z + bv.z);
    o.w = fmaxf(0.f, xv.w + (v.w - mean) * inv * gv.w + bv.w);
    ((float4*)(out + (size_t)r * Dm))[tid] = o;
}

// out[r] = relu( res[r] + LN(t[r]) * g + b )
__global__ __launch_bounds__(128) void ln_res_kernel(
    const float* __restrict__ t, const float* __restrict__ res,
    const float* __restrict__ g, const float* __restrict__ b,
    float* __restrict__ out)
{
    const int r   = blockIdx.x;
    const int tid = threadIdx.x;

    float4 v = ((const float4*)(t + (size_t)r * Dm))[tid];
    float s  = v.x + v.y + v.z + v.w;
    float ss = v.x * v.x + v.y * v.y + v.z * v.z + v.w * v.w;
    float mean, inv;
    block_stats_512(s, ss, mean, inv);

    float4 rv = ((const float4*)(res + (size_t)r * Dm))[tid];
    float4 gv = ((const float4*)g)[tid];
    float4 bv = ((const float4*)b)[tid];
    float4 o;
    o.x = fmaxf(0.f, rv.x + (v.x - mean) * inv * gv.x + bv.x);
    o.y = fmaxf(0.f, rv.y + (v.y - mean) * inv * gv.y + bv.y);
    o.z = fmaxf(0.f, rv.z + (v.z - mean) * inv * gv.z + bv.z);
    o.w = fmaxf(0.f, rv.w + (v.w - mean) * inv * gv.w + bv.w);
    ((float4*)(out + (size_t)r * Dm))[tid] = o;
}

// out[r] = relu( LN(t[r]) * g + b )
__global__ __launch_bounds__(128) void ln_final_kernel(
    const float* __restrict__ t,
    const float* __restrict__ g, const float* __restrict__ b,
    float* __restrict__ out)
{
    const int r   = blockIdx.x;
    const int tid = threadIdx.x;

    float4 v = ((const float4*)(t + (size_t)r * Dm))[tid];
    float s  = v.x + v.y + v.z + v.w;
    float ss = v.x * v.x + v.y * v.y + v.z * v.z + v.w * v.w;
    float mean, inv;
    block_stats_512(s, ss, mean, inv);

    float4 gv = ((const float4*)g)[tid];
    float4 bv = ((const float4*)b)[tid];
    float4 o;
    o.x = fmaxf(0.f, (v.x - mean) * inv * gv.x + bv.x);
    o.y = fmaxf(0.f, (v.y - mean) * inv * gv.y + bv.y);
    o.z = fmaxf(0.f, (v.z - mean) * inv * gv.z + bv.z);
    o.w = fmaxf(0.f, (v.w - mean) * inv * gv.w + bv.w);
    ((float4*)(out + (size_t)r * Dm))[tid] = o;
}

// ---------------------------------------------------------------------------
// Launch
// Inputs (metadata order): x, Wq, bq, Wk, bk, Wv, bv, aW, ab, ag, abeta,
//                          fW, fb, fg, fbeta, dW, db, dg, dbeta
// ---------------------------------------------------------------------------
extern "C" void kernel_launch(void* const* d_in, const int* in_sizes, int n_in,
                              void* d_out, int out_size)
{
    const float* x     = (const float*)d_in[0];
    const float* Wq    = (const float*)d_in[1];
    const float* bq    = (const float*)d_in[2];
    const float* Wk    = (const float*)d_in[3];
    const float* bk    = (const float*)d_in[4];
    const float* Wv    = (const float*)d_in[5];
    const float* bv    = (const float*)d_in[6];
    const float* aW    = (const float*)d_in[7];
    const float* ab    = (const float*)d_in[8];
    const float* ag    = (const float*)d_in[9];
    const float* abeta = (const float*)d_in[10];
    const float* fW    = (const float*)d_in[11];
    const float* fb    = (const float*)d_in[12];
    const float* fg    = (const float*)d_in[13];
    const float* fbeta = (const float*)d_in[14];
    const float* dW    = (const float*)d_in[15];
    const float* db    = (const float*)d_in[16];
    const float* dg    = (const float*)d_in[17];
    const float* dbeta = (const float*)d_in[18];

    float *q, *k, *v, *z, *t, *z2, *o1;
    cudaGetSymbolAddress((void**)&q,  g_q);
    cudaGetSymbolAddress((void**)&k,  g_k);
    cudaGetSymbolAddress((void**)&v,  g_v);
    cudaGetSymbolAddress((void**)&z,  g_z);
    cudaGetSymbolAddress((void**)&t,  g_t);
    cudaGetSymbolAddress((void**)&z2, g_z2);
    cudaGetSymbolAddress((void**)&o1, g_o1);

    // 1) QKV projections on cyclically-shifted x (shift folded into A-loader)
    gemm_kernel<true><<<dim3(HA / 128, TOK / 128), 256>>>(x, Wq, bq, q, TOK, HA, Dm);
    gemm_kernel<true><<<dim3(HA / 128, TOK / 128), 256>>>(x, Wk, bk, k, TOK, HA, Dm);
    gemm_kernel<true><<<dim3(HA / 128, TOK / 128), 256>>>(x, Wv, bv, v, TOK, HA, Dm);

    // 2) windowed attention (WS=4, H=4, A=64)
    attn_kernel<<<TOK / 4, 128>>>(q, k, v, z);

    // 3) attention output projection: t = z @ aW^T + ab
    gemm_kernel<false><<<dim3(Dm / 128, TOK / 128), 256>>>(z, aW, ab, t, TOK, Dm, HA);

    // 4) z2 = relu(x + unshift(LN(t)))
    ln_shift_res_kernel<<<TOK, 128>>>(t, x, ag, abeta, z2);

    // 5) t = z2 @ fW^T + fb
    gemm_kernel<false><<<dim3(Dm / 128, TOK / 128), 256>>>(z2, fW, fb, t, TOK, Dm, Dm);

    // 6) o1 = relu(z2 + LN(t))
    ln_res_kernel<<<TOK, 128>>>(t, z2, fg, fbeta, o1);

    // 7) patch merge is a free reinterpret: o1 as [32768, 1024];
    //    t = merged @ dW^T + db
    gemm_kernel<false><<<dim3(Dm / 128, TOK / 2 / 128), 256>>>(o1, dW, db, t, TOK / 2, Dm, 2 * Dm);

    // 8) out = relu(LN(t))
    ln_final_kernel<<<TOK / 2, 128>>>(t, dg, dbeta, (float*)d_out);
}

// round 4
// speedup vs baseline: 3.1591x; 3.1591x over previous
#include <cuda_runtime.h>
#include <math.h>
#include <cstdint>

// ---------------------------------------------------------------------------
// Problem constants
// ---------------------------------------------------------------------------
static constexpr int TOK = 65536;   // B*M*P
static constexpr int Dm  = 512;
static constexpr int HA  = 256;
static constexpr int QKV = 768;     // fused q|k|v output width

// ---------------------------------------------------------------------------
// Scratch (device globals)
// ---------------------------------------------------------------------------
__device__ float g_qkv[TOK * QKV];
__device__ float g_z [TOK * HA];
__device__ float g_t [TOK * Dm];
__device__ float g_z2[TOK * Dm];
__device__ float g_o1[TOK * Dm];
__device__ float g_xr[TOK * Dm];      // tf32-rounded x
__device__ float g_wr[1310720];       // tf32-rounded weights (concat)
__device__ float g_bqkv[QKV];         // concat bq|bk|bv

// weight offsets in g_wr (Wq|Wk|Wv contiguous = fused [768][512])
static constexpr int OWQ = 0;
static constexpr int OAW = 393216;
static constexpr int OFW = 524288;
static constexpr int ODW = 786432;

// ---------------------------------------------------------------------------
// Helpers
// ---------------------------------------------------------------------------
__device__ __forceinline__ float warp_sum(float v) {
#pragma unroll
    for (int o = 16; o > 0; o >>= 1) v += __shfl_xor_sync(0xffffffffu, v, o);
    return v;
}

// tf32 destination is a .b32 register in PTX — bind as "=r", not "=f".
__device__ __forceinline__ float to_tf32(float x) {
    uint32_t r;
    asm("cvt.rna.tf32.f32 %0, %1;" : "=r"(r) : "f"(x));
    return __uint_as_float(r);
}

// ---------------------------------------------------------------------------
// tf32 rounding kernel (float4 grid-stride)
// ---------------------------------------------------------------------------
__global__ __launch_bounds__(256) void round_tf32_kernel(
    const float* __restrict__ src, float* __restrict__ dst, int n4)
{
    int i = blockIdx.x * blockDim.x + threadIdx.x;
    if (i < n4) {
        float4 v = ((const float4*)src)[i];
        v.x = to_tf32(v.x); v.y = to_tf32(v.y);
        v.z = to_tf32(v.z); v.w = to_tf32(v.w);
        ((float4*)dst)[i] = v;
    }
}

__global__ void concat_bias_kernel(const float* __restrict__ bq,
                                   const float* __restrict__ bk,
                                   const float* __restrict__ bv,
                                   float* __restrict__ out)
{
    int i = threadIdx.x + blockIdx.x * blockDim.x;
    if (i < HA)            out[i]          = bq[i];
    else if (i < 2 * HA)   out[i]          = bk[i - HA];
    else if (i < 3 * HA)   out[i]          = bv[i - 2 * HA];
}

// ---------------------------------------------------------------------------
// tf32 mma.sync GEMM:  C[M,N] = A[M,K] @ W[N,K]^T + bias[N]
// BM=BN=128, BK=32, 3-stage cp.async pipeline, 256 threads (8 warps 4x2),
// warp tile 32x64 via mma.m16n8k8. Smem padded [128][36] (conflict-free).
// SHIFT: remap A row p -> (p+2) mod 256 within each 256-row chunk.
// ---------------------------------------------------------------------------
static constexpr int STAGES     = 3;
static constexpr int LDP        = 36;                   // row pitch (floats)
static constexpr int TILE_F     = 128 * LDP;            // 4608 floats per operand tile
static constexpr int STAGE_F    = 2 * TILE_F;           // A+B
static constexpr int GEMM_SMEM  = STAGES * STAGE_F * 4; // 110592 B

__device__ __forceinline__ void mma_tf32(float* d, const uint32_t* a, const uint32_t* b) {
    asm volatile(
        "mma.sync.aligned.m16n8k8.row.col.f32.tf32.tf32.f32 "
        "{%0,%1,%2,%3}, {%4,%5,%6,%7}, {%8,%9}, {%0,%1,%2,%3};"
        : "+f"(d[0]), "+f"(d[1]), "+f"(d[2]), "+f"(d[3])
        : "r"(a[0]), "r"(a[1]), "r"(a[2]), "r"(a[3]), "r"(b[0]), "r"(b[1]));
}

template<bool SHIFT>
__global__ void __launch_bounds__(256) gemm_mma(
    const float* __restrict__ A, const float* __restrict__ W,
    const float* __restrict__ bias, float* __restrict__ C,
    int M, int N, int K)
{
    extern __shared__ float sm[];

    const int tid  = threadIdx.x;
    const int wid  = tid >> 5;
    const int lane = tid & 31;
    const int wm   = wid & 3;          // 4 M-positions * 32 rows
    const int wn   = wid >> 2;         // 2 N-positions * 64 cols
    const int gid  = lane >> 2;        // 0..7
    const int tig  = lane & 3;         // 0..3
    const int brow = blockIdx.y * 128;
    const int bcol = blockIdx.x * 128;
    const int NIT  = K >> 5;

    auto load_stage = [&](int it, int slot) {
        float* as = sm + slot * STAGE_F;
        float* bs = as + TILE_F;
        const int k0 = it << 5;
#pragma unroll
        for (int i = 0; i < 4; i++) {
            const int u   = i * 256 + tid;      // 0..1023 16B-chunks
            const int row = u >> 3;             // 0..127
            const int c16 = u & 7;              // 8 chunks per 128B row
            const uint32_t doff = (uint32_t)(row * LDP + c16 * 4);
            int ra = brow + row;
            if (SHIFT) ra = (ra & ~255) | ((ra + 2) & 255);
            const float* ga = A + (size_t)ra * K + k0 + c16 * 4;
            const float* gb = W + (size_t)(bcol + row) * K + k0 + c16 * 4;
            uint32_t da = (uint32_t)__cvta_generic_to_shared(as + doff);
            uint32_t db = (uint32_t)__cvta_generic_to_shared(bs + doff);
            asm volatile("cp.async.cg.shared.global [%0], [%1], 16;" :: "r"(da), "l"(ga));
            asm volatile("cp.async.cg.shared.global [%0], [%1], 16;" :: "r"(db), "l"(gb));
        }
        asm volatile("cp.async.commit_group;" ::: "memory");
    };

    float acc[2][8][4];
#pragma unroll
    for (int mt = 0; mt < 2; mt++)
#pragma unroll
        for (int nt = 0; nt < 8; nt++)
#pragma unroll
            for (int r = 0; r < 4; r++) acc[mt][nt][r] = 0.f;

    load_stage(0, 0);
    if (NIT > 1) load_stage(1, 1);

    for (int it = 0; it < NIT; it++) {
        const int slot = it % STAGES;
        if (it == NIT - 1) asm volatile("cp.async.wait_group 0;" ::: "memory");
        else               asm volatile("cp.async.wait_group 1;" ::: "memory");
        __syncthreads();
        if (it + 2 < NIT) load_stage(it + 2, (it + 2) % STAGES);

        const float* as = sm + slot * STAGE_F;
        const float* bs = as + TILE_F;
#pragma unroll
        for (int ks = 0; ks < 4; ks++) {
            const int kb = ks * 8;
            uint32_t af[2][4], bf[8][2];
#pragma unroll
            for (int mt = 0; mt < 2; mt++) {
                const int r0 = wm * 32 + mt * 16 + gid;
                af[mt][0] = __float_as_uint(as[r0 * LDP + kb + tig]);
                af[mt][1] = __float_as_uint(as[(r0 + 8) * LDP + kb + tig]);
                af[mt][2] = __float_as_uint(as[r0 * LDP + kb + tig + 4]);
                af[mt][3] = __float_as_uint(as[(r0 + 8) * LDP + kb + tig + 4]);
            }
#pragma unroll
            for (int nt = 0; nt < 8; nt++) {
                const int n0 = wn * 64 + nt * 8 + gid;
                bf[nt][0] = __float_as_uint(bs[n0 * LDP + kb + tig]);
                bf[nt][1] = __float_as_uint(bs[n0 * LDP + kb + tig + 4]);
            }
#pragma unroll
            for (int mt = 0; mt < 2; mt++)
#pragma unroll
                for (int nt = 0; nt < 8; nt++)
                    mma_tf32(acc[mt][nt], af[mt], bf[nt]);
        }
    }

    // epilogue: D[row][col] layout of m16n8k8 accumulators
#pragma unroll
    for (int mt = 0; mt < 2; mt++) {
        const int r0 = brow + wm * 32 + mt * 16 + gid;
#pragma unroll
        for (int nt = 0; nt < 8; nt++) {
            const int c0 = bcol + wn * 64 + nt * 8 + tig * 2;
            const float b0 = bias[c0], b1 = bias[c0 + 1];
            float2 lo = make_float2(acc[mt][nt][0] + b0, acc[mt][nt][1] + b1);
            float2 hi = make_float2(acc[mt][nt][2] + b0, acc[mt][nt][3] + b1);
            *(float2*)(C + (size_t)r0 * N + c0)       = lo;
            *(float2*)(C + (size_t)(r0 + 8) * N + c0) = hi;
        }
    }
}

// ---------------------------------------------------------------------------
// Windowed attention over fused qkv [TOK][768]; output rounded to tf32.
// ---------------------------------------------------------------------------
__global__ __launch_bounds__(128) void attn_kernel(
    const float* __restrict__ qkv, float* __restrict__ z)
{
    const int win  = blockIdx.x;
    const int h    = threadIdx.x >> 5;
    const int lane = threadIdx.x & 31;
    const int t0   = win * 4;
    const int col  = h * 64 + lane;

    float qr[4][2], kr[4][2], vr[4][2];
#pragma unroll
    for (int i = 0; i < 4; i++) {
        const size_t off = (size_t)(t0 + i) * QKV + col;
        qr[i][0] = qkv[off];            qr[i][1] = qkv[off + 32];
        kr[i][0] = qkv[off + HA];       kr[i][1] = qkv[off + HA + 32];
        vr[i][0] = qkv[off + 2 * HA];   vr[i][1] = qkv[off + 2 * HA + 32];
    }

    float S[4][4];
#pragma unroll
    for (int i = 0; i < 4; i++)
#pragma unroll
        for (int j = 0; j < 4; j++) {
            float p = qr[i][0] * kr[j][0] + qr[i][1] * kr[j][1];
            S[i][j] = warp_sum(p) * 0.125f;
        }

    if ((win & 63) == 63) {
#pragma unroll
        for (int i = 0; i < 4; i++)
#pragma unroll
            for (int j = 0; j < 4; j++)
                if ((i < 2) != (j < 2)) S[i][j] -= 100.0f;
    }

#pragma unroll
    for (int i = 0; i < 4; i++) {
        float m = fmaxf(fmaxf(S[i][0], S[i][1]), fmaxf(S[i][2], S[i][3]));
        float e0 = expf(S[i][0] - m), e1 = expf(S[i][1] - m);
        float e2 = expf(S[i][2] - m), e3 = expf(S[i][3] - m);
        float inv = 1.f / (e0 + e1 + e2 + e3);
        S[i][0] = e0 * inv; S[i][1] = e1 * inv;
        S[i][2] = e2 * inv; S[i][3] = e3 * inv;
    }

#pragma unroll
    for (int i = 0; i < 4; i++) {
        float z0 = S[i][0] * vr[0][0] + S[i][1] * vr[1][0] + S[i][2] * vr[2][0] + S[i][3] * vr[3][0];
        float z1 = S[i][0] * vr[0][1] + S[i][1] * vr[1][1] + S[i][2] * vr[2][1] + S[i][3] * vr[3][1];
        const size_t off = (size_t)(t0 + i) * HA + col;
        z[off]      = to_tf32(z0);
        z[off + 32] = to_tf32(z1);
    }
}

// ---------------------------------------------------------------------------
// LayerNorm kernels
// ---------------------------------------------------------------------------
__device__ __forceinline__ void block_stats_512(float s, float ss, float& mean, float& inv) {
    __shared__ float sh[8];
    const int lane = threadIdx.x & 31, wid = threadIdx.x >> 5;
    s  = warp_sum(s);
    ss = warp_sum(ss);
    if (lane == 0) { sh[wid] = s; sh[4 + wid] = ss; }
    __syncthreads();
    float st  = sh[0] + sh[1] + sh[2] + sh[3];
    float sst = sh[4] + sh[5] + sh[6] + sh[7];
    mean = st * (1.f / 512.f);
    float var = sst * (1.f / 512.f) - mean * mean;
    inv = rsqrtf(var + 1e-5f);
}

// z2[r] = round_tf32( relu( x[r] + LN(t[unshift row]) ) )
__global__ __launch_bounds__(128) void ln_shift_res_kernel(
    const float* __restrict__ t, const float* __restrict__ x,
    const float* __restrict__ g, const float* __restrict__ b,
    float* __restrict__ out)
{
    const int r   = blockIdx.x;
    const int tid = threadIdx.x;
    const int src = (r & ~255) | (((r & 255) + 254) & 255);

    float4 v = ((const float4*)(t + (size_t)src * Dm))[tid];
    float s  = v.x + v.y + v.z + v.w;
    float ss = v.x * v.x + v.y * v.y + v.z * v.z + v.w * v.w;
    float mean, inv;
    block_stats_512(s, ss, mean, inv);

    float4 xv = ((const float4*)(x + (size_t)r * Dm))[tid];
    float4 gv = ((const float4*)g)[tid];
    float4 bv = ((const float4*)b)[tid];
    float4 o;
    o.x = to_tf32(fmaxf(0.f, xv.x + (v.x - mean) * inv * gv.x + bv.x));
    o.y = to_tf32(fmaxf(0.f, xv.y + (v.y - mean) * inv * gv.y + bv.y));
    o.z = to_tf32(fmaxf(0.f, xv.z + (v.z - mean) * inv * gv.z + bv.z));
    o.w = to_tf32(fmaxf(0.f, xv.w + (v.w - mean) * inv * gv.w + bv.w));
    ((float4*)(out + (size_t)r * Dm))[tid] = o;
}

// out[r] = round_tf32( relu( res[r] + LN(t[r]) ) )
__global__ __launch_bounds__(128) void ln_res_kernel(
    const float* __restrict__ t, const float* __restrict__ res,
    const float* __restrict__ g, const float* __restrict__ b,
    float* __restrict__ out)
{
    const int r   = blockIdx.x;
    const int tid = threadIdx.x;

    float4 v = ((const float4*)(t + (size_t)r * Dm))[tid];
    float s  = v.x + v.y + v.z + v.w;
    float ss = v.x * v.x + v.y * v.y + v.z * v.z + v.w * v.w;
    float mean, inv;
    block_stats_512(s, ss, mean, inv);

    float4 rv = ((const float4*)(res + (size_t)r * Dm))[tid];
    float4 gv = ((const float4*)g)[tid];
    float4 bv = ((const float4*)b)[tid];
    float4 o;
    o.x = to_tf32(fmaxf(0.f, rv.x + (v.x - mean) * inv * gv.x + bv.x));
    o.y = to_tf32(fmaxf(0.f, rv.y + (v.y - mean) * inv * gv.y + bv.y));
    o.z = to_tf32(fmaxf(0.f, rv.z + (v.z - mean) * inv * gv.z + bv.z));
    o.w = to_tf32(fmaxf(0.f, rv.w + (v.w - mean) * inv * gv.w + bv.w));
    ((float4*)(out + (size_t)r * Dm))[tid] = o;
}

// out[r] = relu(LN(t[r]))
__global__ __launch_bounds__(128) void ln_final_kernel(
    const float* __restrict__ t,
    const float* __restrict__ g, const float* __restrict__ b,
    float* __restrict__ out)
{
    const int r   = blockIdx.x;
    const int tid = threadIdx.x;

    float4 v = ((const float4*)(t + (size_t)r * Dm))[tid];
    float s  = v.x + v.y + v.z + v.w;
    float ss = v.x * v.x + v.y * v.y + v.z * v.z + v.w * v.w;
    float mean, inv;
    block_stats_512(s, ss, mean, inv);

    float4 gv = ((const float4*)g)[tid];
    float4 bv = ((const float4*)b)[tid];
    float4 o;
    o.x = fmaxf(0.f, (v.x - mean) * inv * gv.x + bv.x);
    o.y = fmaxf(0.f, (v.y - mean) * inv * gv.y + bv.y);
    o.z = fmaxf(0.f, (v.z - mean) * inv * gv.z + bv.z);
    o.w = fmaxf(0.f, (v.w - mean) * inv * gv.w + bv.w);
    ((float4*)(out + (size_t)r * Dm))[tid] = o;
}

// ---------------------------------------------------------------------------
// Launch
// ---------------------------------------------------------------------------
extern "C" void kernel_launch(void* const* d_in, const int* in_sizes, int n_in,
                              void* d_out, int out_size)
{
    const float* x     = (const float*)d_in[0];
    const float* Wq    = (const float*)d_in[1];
    const float* bq    = (const float*)d_in[2];
    const float* Wk    = (const float*)d_in[3];
    const float* bk    = (const float*)d_in[4];
    const float* Wv    = (const float*)d_in[5];
    const float* bv    = (const float*)d_in[6];
    const float* aW    = (const float*)d_in[7];
    const float* ab    = (const float*)d_in[8];
    const float* ag    = (const float*)d_in[9];
    const float* abeta = (const float*)d_in[10];
    const float* fW    = (const float*)d_in[11];
    const float* fb    = (const float*)d_in[12];
    const float* fg    = (const float*)d_in[13];
    const float* fbeta = (const float*)d_in[14];
    const float* dW    = (const float*)d_in[15];
    const float* db    = (const float*)d_in[16];
    const float* dg    = (const float*)d_in[17];
    const float* dbeta = (const float*)d_in[18];

    float *qkv, *z, *t, *z2, *o1, *xr, *wr, *bqkv;
    cudaGetSymbolAddress((void**)&qkv,  g_qkv);
    cudaGetSymbolAddress((void**)&z,    g_z);
    cudaGetSymbolAddress((void**)&t,    g_t);
    cudaGetSymbolAddress((void**)&z2,   g_z2);
    cudaGetSymbolAddress((void**)&o1,   g_o1);
    cudaGetSymbolAddress((void**)&xr,   g_xr);
    cudaGetSymbolAddress((void**)&wr,   g_wr);
    cudaGetSymbolAddress((void**)&bqkv, g_bqkv);

    cudaFuncSetAttribute(gemm_mma<true>,  cudaFuncAttributeMaxDynamicSharedMemorySize, GEMM_SMEM);
    cudaFuncSetAttribute(gemm_mma<false>, cudaFuncAttributeMaxDynamicSharedMemorySize, GEMM_SMEM);

    // 0) round operands to tf32 (RNA): x and all weights; Wq|Wk|Wv land
    //    contiguously in g_wr => fused [768][512] QKV weight.
    round_tf32_kernel<<<(TOK * Dm / 4 + 255) / 256, 256>>>(x, xr, TOK * Dm / 4);
    round_tf32_kernel<<<128, 256>>>(Wq, wr + OWQ,          32768);
    round_tf32_kernel<<<128, 256>>>(Wk, wr + OWQ + 131072, 32768);
    round_tf32_kernel<<<128, 256>>>(Wv, wr + OWQ + 262144, 32768);
    round_tf32_kernel<<<128, 256>>>(aW, wr + OAW,          32768);
    round_tf32_kernel<<<256, 256>>>(fW, wr + OFW,          65536);
    round_tf32_kernel<<<512, 256>>>(dW, wr + ODW,          131072);
    concat_bias_kernel<<<3, 256>>>(bq, bk, bv, bqkv);

    // 1) fused QKV projection on shifted x: [TOK,768]
    gemm_mma<true><<<dim3(QKV / 128, TOK / 128), 256, GEMM_SMEM>>>(
        xr, wr + OWQ, bqkv, qkv, TOK, QKV, Dm);

    // 2) windowed attention
    attn_kernel<<<TOK / 4, 128>>>(qkv, z);

    // 3) t = z @ aW^T + ab
    gemm_mma<false><<<dim3(Dm / 128, TOK / 128), 256, GEMM_SMEM>>>(
        z, wr + OAW, ab, t, TOK, Dm, HA);

    // 4) z2 = relu(x + unshift(LN(t)))
    ln_shift_res_kernel<<<TOK, 128>>>(t, x, ag, abeta, z2);

    // 5) t = z2 @ fW^T + fb
    gemm_mma<false><<<dim3(Dm / 128, TOK / 128), 256, GEMM_SMEM>>>(
        z2, wr + OFW, fb, t, TOK, Dm, Dm);

    // 6) o1 = relu(z2 + LN(t))
    ln_res_kernel<<<TOK, 128>>>(t, z2, fg, fbeta, o1);

    // 7) patch merge = free reinterpret; t = merged @ dW^T + db
    gemm_mma<false><<<dim3(Dm / 128, TOK / 2 / 128), 256, GEMM_SMEM>>>(
        o1, wr + ODW, db, t, TOK / 2, Dm, 2 * Dm);

    // 8) out = relu(LN(t))
    ln_final_kernel<<<TOK / 2, 128>>>(t, dg, dbeta, (float*)d_out);
}

// round 6
// speedup vs baseline: 4.3881x; 1.3890x over previous
#include <cuda_runtime.h>
#include <cuda_fp16.h>
#include <math.h>
#include <cstdint>

// ---------------------------------------------------------------------------
// Problem constants
// ---------------------------------------------------------------------------
static constexpr int TOK = 65536;   // B*M*P
static constexpr int Dm  = 512;
static constexpr int HA  = 256;
static constexpr int QKV = 768;     // fused q|k|v output width

// ---------------------------------------------------------------------------
// Scratch (device globals)
// ---------------------------------------------------------------------------
__device__ float  g_qkv[TOK * QKV];     // fp32 GEMM output (attn input)
__device__ __half g_z  [TOK * HA];      // attn output, half (GEMM operand)
__device__ float  g_t  [TOK * Dm];      // fp32 GEMM output (pre-LN)
__device__ float  g_z2f[TOK * Dm];      // fp32 residual
__device__ __half g_z2h[TOK * Dm];      // half GEMM operand
__device__ __half g_o1 [TOK * Dm];      // half GEMM operand (merged view)
__device__ __half g_xh [TOK * Dm];      // half-rounded x
__device__ __half g_wh [1310720];       // half-rounded weights (concat)
__device__ float  g_bqkv[QKV];          // concat bq|bk|bv

// weight offsets in g_wh (Wq|Wk|Wv contiguous = fused [768][512])
static constexpr int OWQ = 0;
static constexpr int OAW = 393216;
static constexpr int OFW = 524288;
static constexpr int ODW = 786432;

// ---------------------------------------------------------------------------
// Helpers
// ---------------------------------------------------------------------------
__device__ __forceinline__ float warp_sum(float v) {
#pragma unroll
    for (int o = 16; o > 0; o >>= 1) v += __shfl_xor_sync(0xffffffffu, v, o);
    return v;
}

// ---------------------------------------------------------------------------
// fp32 -> fp16 rounding kernel (float4 -> 4 halves per thread)
// ---------------------------------------------------------------------------
__global__ __launch_bounds__(256) void round_h_kernel(
    const float* __restrict__ src, __half* __restrict__ dst, int n4)
{
    int i = blockIdx.x * blockDim.x + threadIdx.x;
    if (i < n4) {
        float4 v = ((const float4*)src)[i];
        __half2 h0 = __floats2half2_rn(v.x, v.y);
        __half2 h1 = __floats2half2_rn(v.z, v.w);
        ((__half2*)dst)[2 * i]     = h0;
        ((__half2*)dst)[2 * i + 1] = h1;
    }
}

__global__ void concat_bias_kernel(const float* __restrict__ bq,
                                   const float* __restrict__ bk,
                                   const float* __restrict__ bv,
                                   float* __restrict__ out)
{
    int i = threadIdx.x + blockIdx.x * blockDim.x;
    if (i < HA)            out[i] = bq[i];
    else if (i < 2 * HA)   out[i] = bk[i - HA];
    else if (i < 3 * HA)   out[i] = bv[i - 2 * HA];
}

// ---------------------------------------------------------------------------
// fp16 mma.sync GEMM:  C[M,N] = A[M,K] @ W[N,K]^T + bias[N]   (A,W half; C f32)
// BM=BN=128, BK=32, 3-stage cp.async pipeline, 256 threads (8 warps 4x2),
// warp tile 32x64 via mma.m16n8k16. Smem rows padded to 40 halves (20 words)
// -> conflict-free fragment loads. SHIFT: A row p -> (p+2) mod 256 per chunk.
// ---------------------------------------------------------------------------
static constexpr int STAGES    = 3;
static constexpr int LDH       = 40;                    // halves per row (32 + 8 pad)
static constexpr int LDW       = 20;                    // words per row
static constexpr int TILE_H    = 128 * LDH;             // 5120 halves
static constexpr int STAGE_H   = 2 * TILE_H;            // A+B
static constexpr int GEMM_SMEM = STAGES * STAGE_H * 2;  // 61440 B

__device__ __forceinline__ void mma_f16(float* d, const uint32_t* a, const uint32_t* b) {
    asm volatile(
        "mma.sync.aligned.m16n8k16.row.col.f32.f16.f16.f32 "
        "{%0,%1,%2,%3}, {%4,%5,%6,%7}, {%8,%9}, {%0,%1,%2,%3};"
        : "+f"(d[0]), "+f"(d[1]), "+f"(d[2]), "+f"(d[3])
        : "r"(a[0]), "r"(a[1]), "r"(a[2]), "r"(a[3]), "r"(b[0]), "r"(b[1]));
}

template<bool SHIFT>
__global__ void __launch_bounds__(256) gemm_mma(
    const __half* __restrict__ A, const __half* __restrict__ W,
    const float* __restrict__ bias, float* __restrict__ C,
    int M, int N, int K)
{
    extern __shared__ __half sm[];

    const int tid  = threadIdx.x;
    const int wid  = tid >> 5;
    const int lane = tid & 31;
    const int wm   = wid & 3;          // 4 M-positions * 32 rows
    const int wn   = wid >> 2;         // 2 N-positions * 64 cols
    const int gid  = lane >> 2;        // 0..7
    const int tig  = lane & 3;         // 0..3
    const int brow = blockIdx.y * 128;
    const int bcol = blockIdx.x * 128;
    const int NIT  = K >> 5;

    auto load_stage = [&](int it, int slot) {
        __half* as = sm + slot * STAGE_H;
        __half* bs = as + TILE_H;
        const int k0 = it << 5;
#pragma unroll
        for (int i = 0; i < 2; i++) {
            const int u   = i * 256 + tid;      // 0..511 16B-chunks
            const int row = u >> 2;             // 0..127
            const int c16 = u & 3;              // 4 chunks (8 halves) per row
            const uint32_t doff = (uint32_t)(row * LDH + c16 * 8);
            int ra = brow + row;
            if (SHIFT) ra = (ra & ~255) | ((ra + 2) & 255);
            const __half* ga = A + (size_t)ra * K + k0 + c16 * 8;
            const __half* gb = W + (size_t)(bcol + row) * K + k0 + c16 * 8;
            uint32_t da = (uint32_t)__cvta_generic_to_shared(as + doff);
            uint32_t db = (uint32_t)__cvta_generic_to_shared(bs + doff);
            asm volatile("cp.async.cg.shared.global [%0], [%1], 16;" :: "r"(da), "l"(ga));
            asm volatile("cp.async.cg.shared.global [%0], [%1], 16;" :: "r"(db), "l"(gb));
        }
        asm volatile("cp.async.commit_group;" ::: "memory");
    };

    float acc[2][8][4];
#pragma unroll
    for (int mt = 0; mt < 2; mt++)
#pragma unroll
        for (int nt = 0; nt < 8; nt++)
#pragma unroll
            for (int r = 0; r < 4; r++) acc[mt][nt][r] = 0.f;

    load_stage(0, 0);
    if (NIT > 1) load_stage(1, 1);

    for (int it = 0; it < NIT; it++) {
        const int slot = it % STAGES;
        if (it == NIT - 1) asm volatile("cp.async.wait_group 0;" ::: "memory");
        else               asm volatile("cp.async.wait_group 1;" ::: "memory");
        __syncthreads();
        if (it + 2 < NIT) load_stage(it + 2, (it + 2) % STAGES);

        const uint32_t* asw = (const uint32_t*)(sm + slot * STAGE_H);
        const uint32_t* bsw = (const uint32_t*)(sm + slot * STAGE_H + TILE_H);
#pragma unroll
        for (int ks = 0; ks < 2; ks++) {
            const int kb = ks * 8;              // word offset of k16 group
            uint32_t af[2][4], bf[8][2];
#pragma unroll
            for (int mt = 0; mt < 2; mt++) {
                const int r0 = wm * 32 + mt * 16 + gid;
                af[mt][0] = asw[r0 * LDW + kb + tig];
                af[mt][1] = asw[(r0 + 8) * LDW + kb + tig];
                af[mt][2] = asw[r0 * LDW + kb + tig + 4];
                af[mt][3] = asw[(r0 + 8) * LDW + kb + tig + 4];
            }
#pragma unroll
            for (int nt = 0; nt < 8; nt++) {
                const int n0 = wn * 64 + nt * 8 + gid;
                bf[nt][0] = bsw[n0 * LDW + kb + tig];
                bf[nt][1] = bsw[n0 * LDW + kb + tig + 4];
            }
#pragma unroll
            for (int mt = 0; mt < 2; mt++)
#pragma unroll
                for (int nt = 0; nt < 8; nt++)
                    mma_f16(acc[mt][nt], af[mt], bf[nt]);
        }
    }

    // epilogue: c0,c1 -> (row gid, cols 2tig,2tig+1); c2,c3 -> row gid+8
#pragma unroll
    for (int mt = 0; mt < 2; mt++) {
        const int r0 = brow + wm * 32 + mt * 16 + gid;
#pragma unroll
        for (int nt = 0; nt < 8; nt++) {
            const int c0 = bcol + wn * 64 + nt * 8 + tig * 2;
            const float b0 = bias[c0], b1 = bias[c0 + 1];
            float2 lo = make_float2(acc[mt][nt][0] + b0, acc[mt][nt][1] + b1);
            float2 hi = make_float2(acc[mt][nt][2] + b0, acc[mt][nt][3] + b1);
            *(float2*)(C + (size_t)r0 * N + c0)       = lo;
            *(float2*)(C + (size_t)(r0 + 8) * N + c0) = hi;
        }
    }
}

// ---------------------------------------------------------------------------
// Windowed attention over fused qkv [TOK][768] (f32); writes half z.
// ---------------------------------------------------------------------------
__global__ __launch_bounds__(128) void attn_kernel(
    const float* __restrict__ qkv, __half* __restrict__ z)
{
    const int win  = blockIdx.x;
    const int h    = threadIdx.x >> 5;
    const int lane = threadIdx.x & 31;
    const int t0   = win * 4;
    const int col  = h * 64 + lane;

    float qr[4][2], kr[4][2], vr[4][2];
#pragma unroll
    for (int i = 0; i < 4; i++) {
        const size_t off = (size_t)(t0 + i) * QKV + col;
        qr[i][0] = qkv[off];            qr[i][1] = qkv[off + 32];
        kr[i][0] = qkv[off + HA];       kr[i][1] = qkv[off + HA + 32];
        vr[i][0] = qkv[off + 2 * HA];   vr[i][1] = qkv[off + 2 * HA + 32];
    }

    float S[4][4];
#pragma unroll
    for (int i = 0; i < 4; i++)
#pragma unroll
        for (int j = 0; j < 4; j++) {
            float p = qr[i][0] * kr[j][0] + qr[i][1] * kr[j][1];
            S[i][j] = warp_sum(p) * 0.125f;
        }

    if ((win & 63) == 63) {
#pragma unroll
        for (int i = 0; i < 4; i++)
#pragma unroll
            for (int j = 0; j < 4; j++)
                if ((i < 2) != (j < 2)) S[i][j] -= 100.0f;
    }

#pragma unroll
    for (int i = 0; i < 4; i++) {
        float m = fmaxf(fmaxf(S[i][0], S[i][1]), fmaxf(S[i][2], S[i][3]));
        float e0 = expf(S[i][0] - m), e1 = expf(S[i][1] - m);
        float e2 = expf(S[i][2] - m), e3 = expf(S[i][3] - m);
        float inv = 1.f / (e0 + e1 + e2 + e3);
        S[i][0] = e0 * inv; S[i][1] = e1 * inv;
        S[i][2] = e2 * inv; S[i][3] = e3 * inv;
    }

#pragma unroll
    for (int i = 0; i < 4; i++) {
        float z0 = S[i][0] * vr[0][0] + S[i][1] * vr[1][0] + S[i][2] * vr[2][0] + S[i][3] * vr[3][0];
        float z1 = S[i][0] * vr[0][1] + S[i][1] * vr[1][1] + S[i][2] * vr[2][1] + S[i][3] * vr[3][1];
        const size_t off = (size_t)(t0 + i) * HA + col;
        z[off]      = __float2half_rn(z0);
        z[off + 32] = __float2half_rn(z1);
    }
}

// ---------------------------------------------------------------------------
// LayerNorm kernels
// ---------------------------------------------------------------------------
__device__ __forceinline__ void block_stats_512(float s, float ss, float& mean, float& inv) {
    __shared__ float sh[8];
    const int lane = threadIdx.x & 31, wid = threadIdx.x >> 5;
    s  = warp_sum(s);
    ss = warp_sum(ss);
    if (lane == 0) { sh[wid] = s; sh[4 + wid] = ss; }
    __syncthreads();
    float st  = sh[0] + sh[1] + sh[2] + sh[3];
    float sst = sh[4] + sh[5] + sh[6] + sh[7];
    mean = st * (1.f / 512.f);
    float var = sst * (1.f / 512.f) - mean * mean;
    inv = rsqrtf(var + 1e-5f);
}

// z2 = relu(x + unshift(LN(t)));  writes float residual + half GEMM operand
__global__ __launch_bounds__(128) void ln_shift_res_kernel(
    const float* __restrict__ t, const float* __restrict__ x,
    const float* __restrict__ g, const float* __restrict__ b,
    float* __restrict__ outf, __half* __restrict__ outh)
{
    const int r   = blockIdx.x;
    const int tid = threadIdx.x;
    const int src = (r & ~255) | (((r & 255) + 254) & 255);

    float4 v = ((const float4*)(t + (size_t)src * Dm))[tid];
    float s  = v.x + v.y + v.z + v.w;
    float ss = v.x * v.x + v.y * v.y + v.z * v.z + v.w * v.w;
    float mean, inv;
    block_stats_512(s, ss, mean, inv);

    float4 xv = ((const float4*)(x + (size_t)r * Dm))[tid];
    float4 gv = ((const float4*)g)[tid];
    float4 bv = ((const float4*)b)[tid];
    float4 o;
    o.x = fmaxf(0.f, xv.x + (v.x - mean) * inv * gv.x + bv.x);
    o.y = fmaxf(0.f, xv.y + (v.y - mean) * inv * gv.y + bv.y);
    o.z = fmaxf(0.f, xv.z + (v.z - mean) * inv * gv.z + bv.z);
    o.w = fmaxf(0.f, xv.w + (v.w - mean) * inv * gv.w + bv.w);
    ((float4*)(outf + (size_t)r * Dm))[tid] = o;
    __half2 h0 = __floats2half2_rn(o.x, o.y);
    __half2 h1 = __floats2half2_rn(o.z, o.w);
    __half2* oh = (__half2*)(outh + (size_t)r * Dm) + 2 * tid;
    oh[0] = h0; oh[1] = h1;
}

// o1 = relu(res + LN(t))  -> half only (GEMM operand)
__global__ __launch_bounds__(128) void ln_res_kernel(
    const float* __restrict__ t, const float* __restrict__ res,
    const float* __restrict__ g, const float* __restrict__ b,
    __half* __restrict__ outh)
{
    const int r   = blockIdx.x;
    const int tid = threadIdx.x;

    float4 v = ((const float4*)(t + (size_t)r * Dm))[tid];
    float s  = v.x + v.y + v.z + v.w;
    float ss = v.x * v.x + v.y * v.y + v.z * v.z + v.w * v.w;
    float mean, inv;
    block_stats_512(s, ss, mean, inv);

    float4 rv = ((const float4*)(res + (size_t)r * Dm))[tid];
    float4 gv = ((const float4*)g)[tid];
    float4 bv = ((const float4*)b)[tid];
    float ox = fmaxf(0.f, rv.x + (v.x - mean) * inv * gv.x + bv.x);
    float oy = fmaxf(0.f, rv.y + (v.y - mean) * inv * gv.y + bv.y);
    float oz = fmaxf(0.f, rv.z + (v.z - mean) * inv * gv.z + bv.z);
    float ow = fmaxf(0.f, rv.w + (v.w - mean) * inv * gv.w + bv.w);
    __half2* oh = (__half2*)(outh + (size_t)r * Dm) + 2 * tid;
    oh[0] = __floats2half2_rn(ox, oy);
    oh[1] = __floats2half2_rn(oz, ow);
}

// out = relu(LN(t))   (final output, fp32)
__global__ __launch_bounds__(128) void ln_final_kernel(
    const float* __restrict__ t,
    const float* __restrict__ g, const float* __restrict__ b,
    float* __restrict__ out)
{
    const int r   = blockIdx.x;
    const int tid = threadIdx.x;

    float4 v = ((const float4*)(t + (size_t)r * Dm))[tid];
    float s  = v.x + v.y + v.z + v.w;
    float ss = v.x * v.x + v.y * v.y + v.z * v.z + v.w * v.w;
    float mean, inv;
    block_stats_512(s, ss, mean, inv);

    float4 gv = ((const float4*)g)[tid];
    float4 bv = ((const float4*)b)[tid];
    float4 o;
    o.x = fmaxf(0.f, (v.x - mean) * inv * gv.x + bv.x);
    o.y = fmaxf(0.f, (v.y - mean) * inv * gv.y + bv.y);
    o.z = fmaxf(0.f, (v.z - mean) * inv * gv.z + bv.z);
    o.w = fmaxf(0.f, (v.w - mean) * inv * gv.w + bv.w);
    ((float4*)(out + (size_t)r * Dm))[tid] = o;
}

// ---------------------------------------------------------------------------
// Launch
// ---------------------------------------------------------------------------
extern "C" void kernel_launch(void* const* d_in, const int* in_sizes, int n_in,
                              void* d_out, int out_size)
{
    const float* x     = (const float*)d_in[0];
    const float* Wq    = (const float*)d_in[1];
    const float* bq    = (const float*)d_in[2];
    const float* Wk    = (const float*)d_in[3];
    const float* bk    = (const float*)d_in[4];
    const float* Wv    = (const float*)d_in[5];
    const float* bv    = (const float*)d_in[6];
    const float* aW    = (const float*)d_in[7];
    const float* ab    = (const float*)d_in[8];
    const float* ag    = (const float*)d_in[9];
    const float* abeta = (const float*)d_in[10];
    const float* fW    = (const float*)d_in[11];
    const float* fb    = (const float*)d_in[12];
    const float* fg    = (const float*)d_in[13];
    const float* fbeta = (const float*)d_in[14];
    const float* dW    = (const float*)d_in[15];
    const float* db    = (const float*)d_in[16];
    const float* dg    = (const float*)d_in[17];
    const float* dbeta = (const float*)d_in[18];

    float *qkv, *t, *z2f, *bqkv;
    __half *z, *z2h, *o1, *xh, *wh;
    cudaGetSymbolAddress((void**)&qkv,  g_qkv);
    cudaGetSymbolAddress((void**)&z,    g_z);
    cudaGetSymbolAddress((void**)&t,    g_t);
    cudaGetSymbolAddress((void**)&z2f,  g_z2f);
    cudaGetSymbolAddress((void**)&z2h,  g_z2h);
    cudaGetSymbolAddress((void**)&o1,   g_o1);
    cudaGetSymbolAddress((void**)&xh,   g_xh);
    cudaGetSymbolAddress((void**)&wh,   g_wh);
    cudaGetSymbolAddress((void**)&bqkv, g_bqkv);

    cudaFuncSetAttribute(gemm_mma<true>,  cudaFuncAttributeMaxDynamicSharedMemorySize, GEMM_SMEM);
    cudaFuncSetAttribute(gemm_mma<false>, cudaFuncAttributeMaxDynamicSharedMemorySize, GEMM_SMEM);

    // 0) round operands to fp16: x and all weights; Wq|Wk|Wv contiguous.
    round_h_kernel<<<(TOK * Dm / 4 + 255) / 256, 256>>>(x, xh, TOK * Dm / 4);
    round_h_kernel<<<128, 256>>>(Wq, wh + OWQ,          32768);
    round_h_kernel<<<128, 256>>>(Wk, wh + OWQ + 131072, 32768);
    round_h_kernel<<<128, 256>>>(Wv, wh + OWQ + 262144, 32768);
    round_h_kernel<<<128, 256>>>(aW, wh + OAW,          32768);
    round_h_kernel<<<256, 256>>>(fW, wh + OFW,          65536);
    round_h_kernel<<<512, 256>>>(dW, wh + ODW,          131072);
    concat_bias_kernel<<<3, 256>>>(bq, bk, bv, bqkv);

    // 1) fused QKV projection on shifted x: [TOK,768] f32
    gemm_mma<true><<<dim3(QKV / 128, TOK / 128), 256, GEMM_SMEM>>>(
        xh, wh + OWQ, bqkv, qkv, TOK, QKV, Dm);

    // 2) windowed attention -> z (half)
    attn_kernel<<<TOK / 4, 128>>>(qkv, z);

    // 3) t = z @ aW^T + ab
    gemm_mma<false><<<dim3(Dm / 128, TOK / 128), 256, GEMM_SMEM>>>(
        z, wh + OAW, ab, t, TOK, Dm, HA);

    // 4) z2 = relu(x + unshift(LN(t)))  (float residual + half operand)
    ln_shift_res_kernel<<<TOK, 128>>>(t, x, ag, abeta, z2f, z2h);

    // 5) t = z2 @ fW^T + fb
    gemm_mma<false><<<dim3(Dm / 128, TOK / 128), 256, GEMM_SMEM>>>(
        z2h, wh + OFW, fb, t, TOK, Dm, Dm);

    // 6) o1 = relu(z2 + LN(t))  (half, GEMM operand only)
    ln_res_kernel<<<TOK, 128>>>(t, z2f, fg, fbeta, o1);

    // 7) patch merge = free reinterpret: o1 as [32768,1024]; t = merged @ dW^T + db
    gemm_mma<false><<<dim3(Dm / 128, TOK / 2 / 128), 256, GEMM_SMEM>>>(
        o1, wh + ODW, db, t, TOK / 2, Dm, 2 * Dm);

    // 8) out = relu(LN(t))
    ln_final_kernel<<<TOK / 2, 128>>>(t, dg, dbeta, (float*)d_out);
}

// round 7
// speedup vs baseline: 4.6462x; 1.0588x over previous
#include <cuda_runtime.h>
#include <cuda_fp16.h>
#include <math.h>
#include <cstdint>

// ---------------------------------------------------------------------------
// Problem constants
// ---------------------------------------------------------------------------
static constexpr int TOK = 65536;   // B*M*P
static constexpr int Dm  = 512;
static constexpr int HA  = 256;
static constexpr int QKV = 768;     // fused q|k|v output width

// ---------------------------------------------------------------------------
// Scratch (device globals)
// ---------------------------------------------------------------------------
__device__ __half g_qkv[TOK * QKV];     // half GEMM output (attn input)
__device__ __half g_z  [TOK * HA];      // attn output, half (GEMM operand)
__device__ float  g_t  [TOK * Dm];      // fp32 GEMM output (pre-LN)
__device__ float  g_z2f[TOK * Dm];      // fp32 residual
__device__ __half g_z2h[TOK * Dm];      // half GEMM operand
__device__ __half g_o1 [TOK * Dm];      // half GEMM operand (merged view)
__device__ __half g_xh [TOK * Dm];      // half-rounded x
__device__ __half g_wh [1310720];       // half-rounded weights (concat)
__device__ float  g_bqkv[QKV];          // concat bq|bk|bv

// weight offsets in g_wh (Wq|Wk|Wv contiguous = fused [768][512])
static constexpr int OWQ = 0;
static constexpr int OAW = 393216;
static constexpr int OFW = 524288;
static constexpr int ODW = 786432;

// ---------------------------------------------------------------------------
// Helpers
// ---------------------------------------------------------------------------
__device__ __forceinline__ float warp_sum(float v) {
#pragma unroll
    for (int o = 16; o > 0; o >>= 1) v += __shfl_xor_sync(0xffffffffu, v, o);
    return v;
}

// ---------------------------------------------------------------------------
// fp32 -> fp16 rounding kernel (float4 -> 4 halves per thread)
// ---------------------------------------------------------------------------
__global__ __launch_bounds__(256) void round_h_kernel(
    const float* __restrict__ src, __half* __restrict__ dst, int n4)
{
    int i = blockIdx.x * blockDim.x + threadIdx.x;
    if (i < n4) {
        float4 v = ((const float4*)src)[i];
        ((__half2*)dst)[2 * i]     = __floats2half2_rn(v.x, v.y);
        ((__half2*)dst)[2 * i + 1] = __floats2half2_rn(v.z, v.w);
    }
}

__global__ void concat_bias_kernel(const float* __restrict__ bq,
                                   const float* __restrict__ bk,
                                   const float* __restrict__ bv,
                                   float* __restrict__ out)
{
    int i = threadIdx.x + blockIdx.x * blockDim.x;
    if (i < HA)            out[i] = bq[i];
    else if (i < 2 * HA)   out[i] = bk[i - HA];
    else if (i < 3 * HA)   out[i] = bv[i - 2 * HA];
}

// ---------------------------------------------------------------------------
// fp16 mma.sync GEMM with ldmatrix fragment loads.
//   C[M,N] = A[M,K] @ W[N,K]^T + bias[N]   (A,W half; acc f32; C float or half)
// BM=BN=128, BK=32, 3-stage cp.async pipeline, 256 threads (8 warps 4x2),
// warp tile 32x64 via mma.m16n8k16. Smem rows padded to 40 halves ->
// ldmatrix row-starts hit 8 distinct bank-quads (conflict-free).
// SHIFT: remap A row p -> (p+2) mod 256 within each 256-row chunk.
// ---------------------------------------------------------------------------
static constexpr int STAGES    = 3;
static constexpr int LDH       = 40;                    // halves per row (32 + 8 pad)
static constexpr int TILE_H    = 128 * LDH;             // 5120 halves per operand tile
static constexpr int STAGE_H   = 2 * TILE_H;            // A+B
static constexpr int GEMM_SMEM = STAGES * STAGE_H * 2;  // 61440 B

__device__ __forceinline__ void mma_f16(float* d, const uint32_t* a, const uint32_t* b) {
    asm volatile(
        "mma.sync.aligned.m16n8k16.row.col.f32.f16.f16.f32 "
        "{%0,%1,%2,%3}, {%4,%5,%6,%7}, {%8,%9}, {%0,%1,%2,%3};"
        : "+f"(d[0]), "+f"(d[1]), "+f"(d[2]), "+f"(d[3])
        : "r"(a[0]), "r"(a[1]), "r"(a[2]), "r"(a[3]), "r"(b[0]), "r"(b[1]));
}

__device__ __forceinline__ void ldsm_x4(uint32_t& r0, uint32_t& r1,
                                        uint32_t& r2, uint32_t& r3, uint32_t addr) {
    asm volatile("ldmatrix.sync.aligned.m8n8.x4.shared.b16 {%0,%1,%2,%3}, [%4];"
                 : "=r"(r0), "=r"(r1), "=r"(r2), "=r"(r3) : "r"(addr));
}

template<bool SHIFT, typename OutT>
__global__ void __launch_bounds__(256) gemm_mma(
    const __half* __restrict__ A, const __half* __restrict__ W,
    const float* __restrict__ bias, OutT* __restrict__ C,
    int M, int N, int K)
{
    extern __shared__ __half sm[];

    const int tid  = threadIdx.x;
    const int wid  = tid >> 5;
    const int lane = tid & 31;
    const int wm   = wid & 3;          // 4 M-positions * 32 rows
    const int wn   = wid >> 2;         // 2 N-positions * 64 cols
    const int gid  = lane >> 2;        // 0..7
    const int tig  = lane & 3;         // 0..3
    const int brow = blockIdx.y * 128;
    const int bcol = blockIdx.x * 128;
    const int NIT  = K >> 5;

    auto load_stage = [&](int it, int slot) {
        __half* as = sm + slot * STAGE_H;
        __half* bs = as + TILE_H;
        const int k0 = it << 5;
#pragma unroll
        for (int i = 0; i < 2; i++) {
            const int u   = i * 256 + tid;      // 0..511 16B-chunks
            const int row = u >> 2;             // 0..127
            const int c16 = u & 3;              // 4 chunks (8 halves) per row
            const uint32_t doff = (uint32_t)(row * LDH + c16 * 8);
            int ra = brow + row;
            if (SHIFT) ra = (ra & ~255) | ((ra + 2) & 255);
            const __half* ga = A + (size_t)ra * K + k0 + c16 * 8;
            const __half* gb = W + (size_t)(bcol + row) * K + k0 + c16 * 8;
            uint32_t da = (uint32_t)__cvta_generic_to_shared(as + doff);
            uint32_t db = (uint32_t)__cvta_generic_to_shared(bs + doff);
            asm volatile("cp.async.cg.shared.global [%0], [%1], 16;" :: "r"(da), "l"(ga));
            asm volatile("cp.async.cg.shared.global [%0], [%1], 16;" :: "r"(db), "l"(gb));
        }
        asm volatile("cp.async.commit_group;" ::: "memory");
    };

    // per-lane ldmatrix address components
    const int lm      = lane & 7;
    const int aRowSel = (lane >> 3) & 1;   // matrices 1,3: +8 m-rows
    const int aKSel   = lane >> 4;         // matrices 2,3: +8 k-halves
    const int bNSel   = lane >> 4;         // matrices 2,3: +8 n-rows (next nt)
    const int bKSel   = (lane >> 3) & 1;   // matrices 1,3: +8 k-halves

    const uint32_t smBase   = (uint32_t)__cvta_generic_to_shared(sm);
    const uint32_t aLaneOff = 2u * ((wm * 32 + aRowSel * 8 + lm) * LDH + aKSel * 8);
    const uint32_t bLaneOff = 2u * ((wn * 64 + bNSel * 8 + lm) * LDH + bKSel * 8)
                              + 2u * TILE_H;

    float acc[2][8][4];
#pragma unroll
    for (int mt = 0; mt < 2; mt++)
#pragma unroll
        for (int nt = 0; nt < 8; nt++)
#pragma unroll
            for (int r = 0; r < 4; r++) acc[mt][nt][r] = 0.f;

    load_stage(0, 0);
    if (NIT > 1) load_stage(1, 1);

    for (int it = 0; it < NIT; it++) {
        const int slot = it % STAGES;
        if (it == NIT - 1) asm volatile("cp.async.wait_group 0;" ::: "memory");
        else               asm volatile("cp.async.wait_group 1;" ::: "memory");
        __syncthreads();
        if (it + 2 < NIT) load_stage(it + 2, (it + 2) % STAGES);

        const uint32_t stage = smBase + (uint32_t)slot * STAGE_H * 2u;
        const uint32_t aB = stage + aLaneOff;
        const uint32_t bB = stage + bLaneOff;
#pragma unroll
        for (int ks = 0; ks < 2; ks++) {
            uint32_t af[2][4], bf[8][2];
#pragma unroll
            for (int mt = 0; mt < 2; mt++)
                ldsm_x4(af[mt][0], af[mt][1], af[mt][2], af[mt][3],
                        aB + 2u * (mt * 16 * LDH + ks * 16));
#pragma unroll
            for (int j = 0; j < 4; j++) {
                uint32_t r0, r1, r2, r3;
                ldsm_x4(r0, r1, r2, r3, bB + 2u * (j * 16 * LDH + ks * 16));
                bf[2 * j][0]     = r0; bf[2 * j][1]     = r1;
                bf[2 * j + 1][0] = r2; bf[2 * j + 1][1] = r3;
            }
#pragma unroll
            for (int mt = 0; mt < 2; mt++)
#pragma unroll
                for (int nt = 0; nt < 8; nt++)
                    mma_f16(acc[mt][nt], af[mt], bf[nt]);
        }
    }

    // epilogue: c0,c1 -> (row gid, cols 2tig,2tig+1); c2,c3 -> row gid+8
#pragma unroll
    for (int mt = 0; mt < 2; mt++) {
        const int r0 = brow + wm * 32 + mt * 16 + gid;
#pragma unroll
        for (int nt = 0; nt < 8; nt++) {
            const int c0 = bcol + wn * 64 + nt * 8 + tig * 2;
            const float b0 = bias[c0], b1 = bias[c0 + 1];
            if constexpr (sizeof(OutT) == 2) {
                __half2* p0 = (__half2*)((__half*)C + (size_t)r0 * N + c0);
                __half2* p1 = (__half2*)((__half*)C + (size_t)(r0 + 8) * N + c0);
                *p0 = __floats2half2_rn(acc[mt][nt][0] + b0, acc[mt][nt][1] + b1);
                *p1 = __floats2half2_rn(acc[mt][nt][2] + b0, acc[mt][nt][3] + b1);
            } else {
                float2 lo = make_float2(acc[mt][nt][0] + b0, acc[mt][nt][1] + b1);
                float2 hi = make_float2(acc[mt][nt][2] + b0, acc[mt][nt][3] + b1);
                *(float2*)((float*)C + (size_t)r0 * N + c0)       = lo;
                *(float2*)((float*)C + (size_t)(r0 + 8) * N + c0) = hi;
            }
        }
    }
}

// ---------------------------------------------------------------------------
// Windowed attention over fused qkv [TOK][768] (half); writes half z.
// ---------------------------------------------------------------------------
__global__ __launch_bounds__(128) void attn_kernel(
    const __half* __restrict__ qkv, __half* __restrict__ z)
{
    const int win  = blockIdx.x;
    const int h    = threadIdx.x >> 5;
    const int lane = threadIdx.x & 31;
    const int t0   = win * 4;
    const int col  = h * 64 + lane;

    float qr[4][2], kr[4][2], vr[4][2];
#pragma unroll
    for (int i = 0; i < 4; i++) {
        const size_t off = (size_t)(t0 + i) * QKV + col;
        qr[i][0] = __half2float(qkv[off]);
        qr[i][1] = __half2float(qkv[off + 32]);
        kr[i][0] = __half2float(qkv[off + HA]);
        kr[i][1] = __half2float(qkv[off + HA + 32]);
        vr[i][0] = __half2float(qkv[off + 2 * HA]);
        vr[i][1] = __half2float(qkv[off + 2 * HA + 32]);
    }

    float S[4][4];
#pragma unroll
    for (int i = 0; i < 4; i++)
#pragma unroll
        for (int j = 0; j < 4; j++) {
            float p = qr[i][0] * kr[j][0] + qr[i][1] * kr[j][1];
            S[i][j] = warp_sum(p) * 0.125f;
        }

    if ((win & 63) == 63) {
#pragma unroll
        for (int i = 0; i < 4; i++)
#pragma unroll
            for (int j = 0; j < 4; j++)
                if ((i < 2) != (j < 2)) S[i][j] -= 100.0f;
    }

#pragma unroll
    for (int i = 0; i < 4; i++) {
        float m = fmaxf(fmaxf(S[i][0], S[i][1]), fmaxf(S[i][2], S[i][3]));
        float e0 = expf(S[i][0] - m), e1 = expf(S[i][1] - m);
        float e2 = expf(S[i][2] - m), e3 = expf(S[i][3] - m);
        float inv = 1.f / (e0 + e1 + e2 + e3);
        S[i][0] = e0 * inv; S[i][1] = e1 * inv;
        S[i][2] = e2 * inv; S[i][3] = e3 * inv;
    }

#pragma unroll
    for (int i = 0; i < 4; i++) {
        float z0 = S[i][0] * vr[0][0] + S[i][1] * vr[1][0] + S[i][2] * vr[2][0] + S[i][3] * vr[3][0];
        float z1 = S[i][0] * vr[0][1] + S[i][1] * vr[1][1] + S[i][2] * vr[2][1] + S[i][3] * vr[3][1];
        const size_t off = (size_t)(t0 + i) * HA + col;
        z[off]      = __float2half_rn(z0);
        z[off + 32] = __float2half_rn(z1);
    }
}

// ---------------------------------------------------------------------------
// LayerNorm kernels
// ---------------------------------------------------------------------------
__device__ __forceinline__ void block_stats_512(float s, float ss, float& mean, float& inv) {
    __shared__ float sh[8];
    const int lane = threadIdx.x & 31, wid = threadIdx.x >> 5;
    s  = warp_sum(s);
    ss = warp_sum(ss);
    if (lane == 0) { sh[wid] = s; sh[4 + wid] = ss; }
    __syncthreads();
    float st  = sh[0] + sh[1] + sh[2] + sh[3];
    float sst = sh[4] + sh[5] + sh[6] + sh[7];
    mean = st * (1.f / 512.f);
    float var = sst * (1.f / 512.f) - mean * mean;
    inv = rsqrtf(var + 1e-5f);
}

// z2 = relu(x + unshift(LN(t)));  writes float residual + half GEMM operand
__global__ __launch_bounds__(128) void ln_shift_res_kernel(
    const float* __restrict__ t, const float* __restrict__ x,
    const float* __restrict__ g, const float* __restrict__ b,
    float* __restrict__ outf, __half* __restrict__ outh)
{
    const int r   = blockIdx.x;
    const int tid = threadIdx.x;
    const int src = (r & ~255) | (((r & 255) + 254) & 255);

    float4 v = ((const float4*)(t + (size_t)src * Dm))[tid];
    float s  = v.x + v.y + v.z + v.w;
    float ss = v.x * v.x + v.y * v.y + v.z * v.z + v.w * v.w;
    float mean, inv;
    block_stats_512(s, ss, mean, inv);

    float4 xv = ((const float4*)(x + (size_t)r * Dm))[tid];
    float4 gv = ((const float4*)g)[tid];
    float4 bv = ((const float4*)b)[tid];
    float4 o;
    o.x = fmaxf(0.f, xv.x + (v.x - mean) * inv * gv.x + bv.x);
    o.y = fmaxf(0.f, xv.y + (v.y - mean) * inv * gv.y + bv.y);
    o.z = fmaxf(0.f, xv.z + (v.z - mean) * inv * gv.z + bv.z);
    o.w = fmaxf(0.f, xv.w + (v.w - mean) * inv * gv.w + bv.w);
    ((float4*)(outf + (size_t)r * Dm))[tid] = o;
    __half2* oh = (__half2*)(outh + (size_t)r * Dm) + 2 * tid;
    oh[0] = __floats2half2_rn(o.x, o.y);
    oh[1] = __floats2half2_rn(o.z, o.w);
}

// o1 = relu(res + LN(t))  -> half only (GEMM operand)
__global__ __launch_bounds__(128) void ln_res_kernel(
    const float* __restrict__ t, const float* __restrict__ res,
    const float* __restrict__ g, const float* __restrict__ b,
    __half* __restrict__ outh)
{
    const int r   = blockIdx.x;
    const int tid = threadIdx.x;

    float4 v = ((const float4*)(t + (size_t)r * Dm))[tid];
    float s  = v.x + v.y + v.z + v.w;
    float ss = v.x * v.x + v.y * v.y + v.z * v.z + v.w * v.w;
    float mean, inv;
    block_stats_512(s, ss, mean, inv);

    float4 rv = ((const float4*)(res + (size_t)r * Dm))[tid];
    float4 gv = ((const float4*)g)[tid];
    float4 bv = ((const float4*)b)[tid];
    float ox = fmaxf(0.f, rv.x + (v.x - mean) * inv * gv.x + bv.x);
    float oy = fmaxf(0.f, rv.y + (v.y - mean) * inv * gv.y + bv.y);
    float oz = fmaxf(0.f, rv.z + (v.z - mean) * inv * gv.z + bv.z);
    float ow = fmaxf(0.f, rv.w + (v.w - mean) * inv * gv.w + bv.w);
    __half2* oh = (__half2*)(outh + (size_t)r * Dm) + 2 * tid;
    oh[0] = __floats2half2_rn(ox, oy);
    oh[1] = __floats2half2_rn(oz, ow);
}

// out = relu(LN(t))   (final output, fp32)
__global__ __launch_bounds__(128) void ln_final_kernel(
    const float* __restrict__ t,
    const float* __restrict__ g, const float* __restrict__ b,
    float* __restrict__ out)
{
    const int r   = blockIdx.x;
    const int tid = threadIdx.x;

    float4 v = ((const float4*)(t + (size_t)r * Dm))[tid];
    float s  = v.x + v.y + v.z + v.w;
    float ss = v.x * v.x + v.y * v.y + v.z * v.z + v.w * v.w;
    float mean, inv;
    block_stats_512(s, ss, mean, inv);

    float4 gv = ((const float4*)g)[tid];
    float4 bv = ((const float4*)b)[tid];
    float4 o;
    o.x = fmaxf(0.f, (v.x - mean) * inv * gv.x + bv.x);
    o.y = fmaxf(0.f, (v.y - mean) * inv * gv.y + bv.y);
    o.z = fmaxf(0.f, (v.z - mean) * inv * gv.z + bv.z);
    o.w = fmaxf(0.f, (v.w - mean) * inv * gv.w + bv.w);
    ((float4*)(out + (size_t)r * Dm))[tid] = o;
}

// ---------------------------------------------------------------------------
// Launch
// ---------------------------------------------------------------------------
extern "C" void kernel_launch(void* const* d_in, const int* in_sizes, int n_in,
                              void* d_out, int out_size)
{
    const float* x     = (const float*)d_in[0];
    const float* Wq    = (const float*)d_in[1];
    const float* bq    = (const float*)d_in[2];
    const float* Wk    = (const float*)d_in[3];
    const float* bk    = (const float*)d_in[4];
    const float* Wv    = (const float*)d_in[5];
    const float* bv    = (const float*)d_in[6];
    const float* aW    = (const float*)d_in[7];
    const float* ab    = (const float*)d_in[8];
    const float* ag    = (const float*)d_in[9];
    const float* abeta = (const float*)d_in[10];
    const float* fW    = (const float*)d_in[11];
    const float* fb    = (const float*)d_in[12];
    const float* fg    = (const float*)d_in[13];
    const float* fbeta = (const float*)d_in[14];
    const float* dW    = (const float*)d_in[15];
    const float* db    = (const float*)d_in[16];
    const float* dg    = (const float*)d_in[17];
    const float* dbeta = (const float*)d_in[18];

    float *t, *z2f, *bqkv;
    __half *qkv, *z, *z2h, *o1, *xh, *wh;
    cudaGetSymbolAddress((void**)&qkv,  g_qkv);
    cudaGetSymbolAddress((void**)&z,    g_z);
    cudaGetSymbolAddress((void**)&t,    g_t);
    cudaGetSymbolAddress((void**)&z2f,  g_z2f);
    cudaGetSymbolAddress((void**)&z2h,  g_z2h);
    cudaGetSymbolAddress((void**)&o1,   g_o1);
    cudaGetSymbolAddress((void**)&xh,   g_xh);
    cudaGetSymbolAddress((void**)&wh,   g_wh);
    cudaGetSymbolAddress((void**)&bqkv, g_bqkv);

    cudaFuncSetAttribute(gemm_mma<true, __half>, cudaFuncAttributeMaxDynamicSharedMemorySize, GEMM_SMEM);
    cudaFuncSetAttribute(gemm_mma<false, float>, cudaFuncAttributeMaxDynamicSharedMemorySize, GEMM_SMEM);

    // 0) round operands to fp16: x and all weights; Wq|Wk|Wv contiguous.
    round_h_kernel<<<(TOK * Dm / 4 + 255) / 256, 256>>>(x, xh, TOK * Dm / 4);
    round_h_kernel<<<128, 256>>>(Wq, wh + OWQ,          32768);
    round_h_kernel<<<128, 256>>>(Wk, wh + OWQ + 131072, 32768);
    round_h_kernel<<<128, 256>>>(Wv, wh + OWQ + 262144, 32768);
    round_h_kernel<<<128, 256>>>(aW, wh + OAW,          32768);
    round_h_kernel<<<256, 256>>>(fW, wh + OFW,          65536);
    round_h_kernel<<<512, 256>>>(dW, wh + ODW,          131072);
    concat_bias_kernel<<<3, 256>>>(bq, bk, bv, bqkv);

    // 1) fused QKV projection on shifted x: [TOK,768] half
    gemm_mma<true, __half><<<dim3(QKV / 128, TOK / 128), 256, GEMM_SMEM>>>(
        xh, wh + OWQ, bqkv, qkv, TOK, QKV, Dm);

    // 2) windowed attention -> z (half)
    attn_kernel<<<TOK / 4, 128>>>(qkv, z);

    // 3) t = z @ aW^T + ab
    gemm_mma<false, float><<<dim3(Dm / 128, TOK / 128), 256, GEMM_SMEM>>>(
        z, wh + OAW, ab, t, TOK, Dm, HA);

    // 4) z2 = relu(x + unshift(LN(t)))  (float residual + half operand)
    ln_shift_res_kernel<<<TOK, 128>>>(t, x, ag, abeta, z2f, z2h);

    // 5) t = z2 @ fW^T + fb
    gemm_mma<false, float><<<dim3(Dm / 128, TOK / 128), 256, GEMM_SMEM>>>(
        z2h, wh + OFW, fb, t, TOK, Dm, Dm);

    // 6) o1 = relu(z2 + LN(t))  (half, GEMM operand only)
    ln_res_kernel<<<TOK, 128>>>(t, z2f, fg, fbeta, o1);

    // 7) patch merge = free reinterpret: o1 as [32768,1024]; t = merged @ dW^T + db
    gemm_mma<false, float><<<dim3(Dm / 128, TOK / 2 / 128), 256, GEMM_SMEM>>>(
        o1, wh + ODW, db, t, TOK / 2, Dm, 2 * Dm);

    // 8) out = relu(LN(t))
    ln_final_kernel<<<TOK / 2, 128>>>(t, dg, dbeta, (float*)d_out);
}

// round 10
// speedup vs baseline: 4.9010x; 1.0548x over previous
#include <cuda_runtime.h>
#include <cuda_fp16.h>
#include <math.h>
#include <cstdint>

// ---------------------------------------------------------------------------
// Problem constants
// ---------------------------------------------------------------------------
static constexpr int TOK = 65536;   // B*M*P
static constexpr int Dm  = 512;
static constexpr int HA  = 256;
static constexpr int QKV = 768;     // fused q|k|v output width

// ---------------------------------------------------------------------------
// Scratch (device globals)
// ---------------------------------------------------------------------------
__device__ __half g_qkv[TOK * QKV];     // half GEMM output (attn input)
__device__ __half g_z  [TOK * HA];      // attn output, half (GEMM operand)
__device__ __half g_th [TOK * Dm];      // half GEMM output (pre-LN, steps 3/5)
__device__ float  g_t  [TOK * Dm];      // fp32 GEMM output (final, step 7)
__device__ __half g_z2h[TOK * Dm];      // half z2 (GEMM operand + residual)
__device__ __half g_o1 [TOK * Dm];      // half GEMM operand (merged view)
__device__ __half g_xh [TOK * Dm];      // half-rounded x
__device__ __half g_wh [1310720];       // half-rounded weights (concat)
__device__ float  g_bqkv[QKV];          // concat bq|bk|bv

// weight offsets in g_wh (Wq|Wk|Wv contiguous = fused [768][512])
static constexpr int OWQ = 0;
static constexpr int OAW = 393216;
static constexpr int OFW = 524288;
static constexpr int ODW = 786432;

// ---------------------------------------------------------------------------
// Helpers
// ---------------------------------------------------------------------------
__device__ __forceinline__ float warp_sum(float v) {
#pragma unroll
    for (int o = 16; o > 0; o >>= 1) v += __shfl_xor_sync(0xffffffffu, v, o);
    return v;
}

// ---------------------------------------------------------------------------
// fp32 -> fp16 rounding kernel (float4 -> 4 halves per thread)
// ---------------------------------------------------------------------------
__global__ __launch_bounds__(256) void round_h_kernel(
    const float* __restrict__ src, __half* __restrict__ dst, int n4)
{
    int i = blockIdx.x * blockDim.x + threadIdx.x;
    if (i < n4) {
        float4 v = ((const float4*)src)[i];
        ((__half2*)dst)[2 * i]     = __floats2half2_rn(v.x, v.y);
        ((__half2*)dst)[2 * i + 1] = __floats2half2_rn(v.z, v.w);
    }
}

__global__ void concat_bias_kernel(const float* __restrict__ bq,
                                   const float* __restrict__ bk,
                                   const float* __restrict__ bv,
                                   float* __restrict__ out)
{
    int i = threadIdx.x + blockIdx.x * blockDim.x;
    if (i < HA)            out[i] = bq[i];
    else if (i < 2 * HA)   out[i] = bk[i - HA];
    else if (i < 3 * HA)   out[i] = bv[i - 2 * HA];
}

// ---------------------------------------------------------------------------
// fp16 mma.sync GEMM with ldmatrix fragment loads (unchanged from R7).
// ---------------------------------------------------------------------------
static constexpr int STAGES    = 3;
static constexpr int LDH       = 40;                    // halves per row (32 + 8 pad)
static constexpr int TILE_H    = 128 * LDH;             // 5120 halves per operand tile
static constexpr int STAGE_H   = 2 * TILE_H;            // A+B
static constexpr int GEMM_SMEM = STAGES * STAGE_H * 2;  // 61440 B

__device__ __forceinline__ void mma_f16(float* d, const uint32_t* a, const uint32_t* b) {
    asm volatile(
        "mma.sync.aligned.m16n8k16.row.col.f32.f16.f16.f32 "
        "{%0,%1,%2,%3}, {%4,%5,%6,%7}, {%8,%9}, {%0,%1,%2,%3};"
        : "+f"(d[0]), "+f"(d[1]), "+f"(d[2]), "+f"(d[3])
        : "r"(a[0]), "r"(a[1]), "r"(a[2]), "r"(a[3]), "r"(b[0]), "r"(b[1]));
}

__device__ __forceinline__ void ldsm_x4(uint32_t& r0, uint32_t& r1,
                                        uint32_t& r2, uint32_t& r3, uint32_t addr) {
    asm volatile("ldmatrix.sync.aligned.m8n8.x4.shared.b16 {%0,%1,%2,%3}, [%4];"
                 : "=r"(r0), "=r"(r1), "=r"(r2), "=r"(r3) : "r"(addr));
}

template<bool SHIFT, typename OutT>
__global__ void __launch_bounds__(256) gemm_mma(
    const __half* __restrict__ A, const __half* __restrict__ W,
    const float* __restrict__ bias, OutT* __restrict__ C,
    int M, int N, int K)
{
    extern __shared__ __half sm[];

    const int tid  = threadIdx.x;
    const int wid  = tid >> 5;
    const int lane = tid & 31;
    const int wm   = wid & 3;
    const int wn   = wid >> 2;
    const int gid  = lane >> 2;
    const int tig  = lane & 3;
    const int brow = blockIdx.y * 128;
    const int bcol = blockIdx.x * 128;
    const int NIT  = K >> 5;

    auto load_stage = [&](int it, int slot) {
        __half* as = sm + slot * STAGE_H;
        __half* bs = as + TILE_H;
        const int k0 = it << 5;
#pragma unroll
        for (int i = 0; i < 2; i++) {
            const int u   = i * 256 + tid;
            const int row = u >> 2;
            const int c16 = u & 3;
            const uint32_t doff = (uint32_t)(row * LDH + c16 * 8);
            int ra = brow + row;
            if (SHIFT) ra = (ra & ~255) | ((ra + 2) & 255);
            const __half* ga = A + (size_t)ra * K + k0 + c16 * 8;
            const __half* gb = W + (size_t)(bcol + row) * K + k0 + c16 * 8;
            uint32_t da = (uint32_t)__cvta_generic_to_shared(as + doff);
            uint32_t db = (uint32_t)__cvta_generic_to_shared(bs + doff);
            asm volatile("cp.async.cg.shared.global [%0], [%1], 16;" :: "r"(da), "l"(ga));
            asm volatile("cp.async.cg.shared.global [%0], [%1], 16;" :: "r"(db), "l"(gb));
        }
        asm volatile("cp.async.commit_group;" ::: "memory");
    };

    const int lm      = lane & 7;
    const int aRowSel = (lane >> 3) & 1;
    const int aKSel   = lane >> 4;
    const int bNSel   = lane >> 4;
    const int bKSel   = (lane >> 3) & 1;

    const uint32_t smBase   = (uint32_t)__cvta_generic_to_shared(sm);
    const uint32_t aLaneOff = 2u * ((wm * 32 + aRowSel * 8 + lm) * LDH + aKSel * 8);
    const uint32_t bLaneOff = 2u * ((wn * 64 + bNSel * 8 + lm) * LDH + bKSel * 8)
                              + 2u * TILE_H;

    float acc[2][8][4];
#pragma unroll
    for (int mt = 0; mt < 2; mt++)
#pragma unroll
        for (int nt = 0; nt < 8; nt++)
#pragma unroll
            for (int r = 0; r < 4; r++) acc[mt][nt][r] = 0.f;

    load_stage(0, 0);
    if (NIT > 1) load_stage(1, 1);

    for (int it = 0; it < NIT; it++) {
        const int slot = it % STAGES;
        if (it == NIT - 1) asm volatile("cp.async.wait_group 0;" ::: "memory");
        else               asm volatile("cp.async.wait_group 1;" ::: "memory");
        __syncthreads();
        if (it + 2 < NIT) load_stage(it + 2, (it + 2) % STAGES);

        const uint32_t stage = smBase + (uint32_t)slot * STAGE_H * 2u;
        const uint32_t aB = stage + aLaneOff;
        const uint32_t bB = stage + bLaneOff;
#pragma unroll
        for (int ks = 0; ks < 2; ks++) {
            uint32_t af[2][4], bf[8][2];
#pragma unroll
            for (int mt = 0; mt < 2; mt++)
                ldsm_x4(af[mt][0], af[mt][1], af[mt][2], af[mt][3],
                        aB + 2u * (mt * 16 * LDH + ks * 16));
#pragma unroll
            for (int j = 0; j < 4; j++) {
                uint32_t r0, r1, r2, r3;
                ldsm_x4(r0, r1, r2, r3, bB + 2u * (j * 16 * LDH + ks * 16));
                bf[2 * j][0]     = r0; bf[2 * j][1]     = r1;
                bf[2 * j + 1][0] = r2; bf[2 * j + 1][1] = r3;
            }
#pragma unroll
            for (int mt = 0; mt < 2; mt++)
#pragma unroll
                for (int nt = 0; nt < 8; nt++)
                    mma_f16(acc[mt][nt], af[mt], bf[nt]);
        }
    }

#pragma unroll
    for (int mt = 0; mt < 2; mt++) {
        const int r0 = brow + wm * 32 + mt * 16 + gid;
#pragma unroll
        for (int nt = 0; nt < 8; nt++) {
            const int c0 = bcol + wn * 64 + nt * 8 + tig * 2;
            const float b0 = bias[c0], b1 = bias[c0 + 1];
            if constexpr (sizeof(OutT) == 2) {
                __half2* p0 = (__half2*)((__half*)C + (size_t)r0 * N + c0);
                __half2* p1 = (__half2*)((__half*)C + (size_t)(r0 + 8) * N + c0);
                *p0 = __floats2half2_rn(acc[mt][nt][0] + b0, acc[mt][nt][1] + b1);
                *p1 = __floats2half2_rn(acc[mt][nt][2] + b0, acc[mt][nt][3] + b1);
            } else {
                float2 lo = make_float2(acc[mt][nt][0] + b0, acc[mt][nt][1] + b1);
                float2 hi = make_float2(acc[mt][nt][2] + b0, acc[mt][nt][3] + b1);
                *(float2*)((float*)C + (size_t)r0 * N + c0)       = lo;
                *(float2*)((float*)C + (size_t)(r0 + 8) * N + c0) = hi;
            }
        }
    }
}

// ---------------------------------------------------------------------------
// Windowed attention over fused qkv [TOK][768] (half); writes half z.
// ---------------------------------------------------------------------------
__global__ __launch_bounds__(128) void attn_kernel(
    const __half* __restrict__ qkv, __half* __restrict__ z)
{
    const int win  = blockIdx.x;
    const int h    = threadIdx.x >> 5;
    const int lane = threadIdx.x & 31;
    const int t0   = win * 4;
    const int col  = h * 64 + lane;

    float qr[4][2], kr[4][2], vr[4][2];
#pragma unroll
    for (int i = 0; i < 4; i++) {
        const size_t off = (size_t)(t0 + i) * QKV + col;
        qr[i][0] = __half2float(qkv[off]);
        qr[i][1] = __half2float(qkv[off + 32]);
        kr[i][0] = __half2float(qkv[off + HA]);
        kr[i][1] = __half2float(qkv[off + HA + 32]);
        vr[i][0] = __half2float(qkv[off + 2 * HA]);
        vr[i][1] = __half2float(qkv[off + 2 * HA + 32]);
    }

    float S[4][4];
#pragma unroll
    for (int i = 0; i < 4; i++)
#pragma unroll
        for (int j = 0; j < 4; j++) {
            float p = qr[i][0] * kr[j][0] + qr[i][1] * kr[j][1];
            S[i][j] = warp_sum(p) * 0.125f;
        }

    if ((win & 63) == 63) {
#pragma unroll
        for (int i = 0; i < 4; i++)
#pragma unroll
            for (int j = 0; j < 4; j++)
                if ((i < 2) != (j < 2)) S[i][j] -= 100.0f;
    }

#pragma unroll
    for (int i = 0; i < 4; i++) {
        float m = fmaxf(fmaxf(S[i][0], S[i][1]), fmaxf(S[i][2], S[i][3]));
        float e0 = expf(S[i][0] - m), e1 = expf(S[i][1] - m);
        float e2 = expf(S[i][2] - m), e3 = expf(S[i][3] - m);
        float inv = 1.f / (e0 + e1 + e2 + e3);
        S[i][0] = e0 * inv; S[i][1] = e1 * inv;
        S[i][2] = e2 * inv; S[i][3] = e3 * inv;
    }

#pragma unroll
    for (int i = 0; i < 4; i++) {
        float z0 = S[i][0] * vr[0][0] + S[i][1] * vr[1][0] + S[i][2] * vr[2][0] + S[i][3] * vr[3][0];
        float z1 = S[i][0] * vr[0][1] + S[i][1] * vr[1][1] + S[i][2] * vr[2][1] + S[i][3] * vr[3][1];
        const size_t off = (size_t)(t0 + i) * HA + col;
        z[off]      = __float2half_rn(z0);
        z[off + 32] = __float2half_rn(z1);
    }
}

// ---------------------------------------------------------------------------
// LayerNorm kernels. Half-t variants: 128 threads x 4 halves (uint2) = 512.
// ---------------------------------------------------------------------------
__device__ __forceinline__ void block_stats_512(float s, float ss, float& mean, float& inv) {
    __shared__ float sh[8];
    const int lane = threadIdx.x & 31, wid = threadIdx.x >> 5;
    s  = warp_sum(s);
    ss = warp_sum(ss);
    if (lane == 0) { sh[wid] = s; sh[4 + wid] = ss; }
    __syncthreads();
    float st  = sh[0] + sh[1] + sh[2] + sh[3];
    float sst = sh[4] + sh[5] + sh[6] + sh[7];
    mean = st * (1.f / 512.f);
    float var = sst * (1.f / 512.f) - mean * mean;
    inv = rsqrtf(var + 1e-5f);
}

// unpack 4 halves from a uint2
__device__ __forceinline__ void unpack4(uint2 u, float* f) {
    __half2 h0 = *(__half2*)&u.x;
    __half2 h1 = *(__half2*)&u.y;
    f[0] = __low2float(h0); f[1] = __high2float(h0);
    f[2] = __low2float(h1); f[3] = __high2float(h1);
}

// z2 = relu(x + unshift(LN(t_h)));  writes half z2 only
__global__ __launch_bounds__(128) void ln_shift_res_kernel(
    const __half* __restrict__ t, const float* __restrict__ x,
    const float* __restrict__ g, const float* __restrict__ b,
    __half* __restrict__ outh)
{
    const int r   = blockIdx.x;
    const int tid = threadIdx.x;
    const int src = (r & ~255) | (((r & 255) + 254) & 255);

    uint2 tv = ((const uint2*)(t + (size_t)src * Dm))[tid];
    float f[4];
    unpack4(tv, f);
    float s  = f[0] + f[1] + f[2] + f[3];
    float ss = f[0]*f[0] + f[1]*f[1] + f[2]*f[2] + f[3]*f[3];
    float mean, inv;
    block_stats_512(s, ss, mean, inv);

    float4 xv = ((const float4*)(x + (size_t)r * Dm))[tid];
    float4 gv = ((const float4*)g)[tid];
    float4 bv = ((const float4*)b)[tid];
    float ox = fmaxf(0.f, xv.x + (f[0] - mean) * inv * gv.x + bv.x);
    float oy = fmaxf(0.f, xv.y + (f[1] - mean) * inv * gv.y + bv.y);
    float oz = fmaxf(0.f, xv.z + (f[2] - mean) * inv * gv.z + bv.z);
    float ow = fmaxf(0.f, xv.w + (f[3] - mean) * inv * gv.w + bv.w);
    uint2 ov;
    *(__half2*)&ov.x = __floats2half2_rn(ox, oy);
    *(__half2*)&ov.y = __floats2half2_rn(oz, ow);
    ((uint2*)(outh + (size_t)r * Dm))[tid] = ov;
}

// o1 = relu(z2 + LN(t_h))  (residual z2 is half)
__global__ __launch_bounds__(128) void ln_res_kernel(
    const __half* __restrict__ t, const __half* __restrict__ res,
    const float* __restrict__ g, const float* __restrict__ b,
    __half* __restrict__ outh)
{
    const int r   = blockIdx.x;
    const int tid = threadIdx.x;

    uint2 tv = ((const uint2*)(t + (size_t)r * Dm))[tid];
    float f[4];
    unpack4(tv, f);
    float s  = f[0] + f[1] + f[2] + f[3];
    float ss = f[0]*f[0] + f[1]*f[1] + f[2]*f[2] + f[3]*f[3];
    float mean, inv;
    block_stats_512(s, ss, mean, inv);

    uint2 rv = ((const uint2*)(res + (size_t)r * Dm))[tid];
    float rf[4];
    unpack4(rv, rf);
    float4 gv = ((const float4*)g)[tid];
    float4 bv = ((const float4*)b)[tid];
    float ox = fmaxf(0.f, rf[0] + (f[0] - mean) * inv * gv.x + bv.x);
    float oy = fmaxf(0.f, rf[1] + (f[1] - mean) * inv * gv.y + bv.y);
    float oz = fmaxf(0.f, rf[2] + (f[2] - mean) * inv * gv.z + bv.z);
    float ow = fmaxf(0.f, rf[3] + (f[3] - mean) * inv * gv.w + bv.w);
    uint2 ov;
    *(__half2*)&ov.x = __floats2half2_rn(ox, oy);
    *(__half2*)&ov.y = __floats2half2_rn(oz, ow);
    ((uint2*)(outh + (size_t)r * Dm))[tid] = ov;
}

// out = relu(LN(t_f))   (final output, fp32 in and out)
__global__ __launch_bounds__(128) void ln_final_kernel(
    const float* __restrict__ t,
    const float* __restrict__ g, const float* __restrict__ b,
    float* __restrict__ out)
{
    const int r   = blockIdx.x;
    const int tid = threadIdx.x;

    float4 v = ((const float4*)(t + (size_t)r * Dm))[tid];
    float s  = v.x + v.y + v.z + v.w;
    float ss = v.x * v.x + v.y * v.y + v.z * v.z + v.w * v.w;
    float mean, inv;
    block_stats_512(s, ss, mean, inv);

    float4 gv = ((const float4*)g)[tid];
    float4 bv = ((const float4*)b)[tid];
    float4 o;
    o.x = fmaxf(0.f, (v.x - mean) * inv * gv.x + bv.x);
    o.y = fmaxf(0.f, (v.y - mean) * inv * gv.y + bv.y);
    o.z = fmaxf(0.f, (v.z - mean) * inv * gv.z + bv.z);
    o.w = fmaxf(0.f, (v.w - mean) * inv * gv.w + bv.w);
    ((float4*)(out + (size_t)r * Dm))[tid] = o;
}

// ---------------------------------------------------------------------------
// Launch
// ---------------------------------------------------------------------------
extern "C" void kernel_launch(void* const* d_in, const int* in_sizes, int n_in,
                              void* d_out, int out_size)
{
    const float* x     = (const float*)d_in[0];
    const float* Wq    = (const float*)d_in[1];
    const float* bq    = (const float*)d_in[2];
    const float* Wk    = (const float*)d_in[3];
    const float* bk    = (const float*)d_in[4];
    const float* Wv    = (const float*)d_in[5];
    const float* bv    = (const float*)d_in[6];
    const float* aW    = (const float*)d_in[7];
    const float* ab    = (const float*)d_in[8];
    const float* ag    = (const float*)d_in[9];
    const float* abeta = (const float*)d_in[10];
    const float* fW    = (const float*)d_in[11];
    const float* fb    = (const float*)d_in[12];
    const float* fg    = (const float*)d_in[13];
    const float* fbeta = (const float*)d_in[14];
    const float* dW    = (const float*)d_in[15];
    const float* db    = (const float*)d_in[16];
    const float* dg    = (const float*)d_in[17];
    const float* dbeta = (const float*)d_in[18];

    float *t, *bqkv;
    __half *qkv, *z, *th, *z2h, *o1, *xh, *wh;
    cudaGetSymbolAddress((void**)&qkv,  g_qkv);
    cudaGetSymbolAddress((void**)&z,    g_z);
    cudaGetSymbolAddress((void**)&th,   g_th);
    cudaGetSymbolAddress((void**)&t,    g_t);
    cudaGetSymbolAddress((void**)&z2h,  g_z2h);
    cudaGetSymbolAddress((void**)&o1,   g_o1);
    cudaGetSymbolAddress((void**)&xh,   g_xh);
    cudaGetSymbolAddress((void**)&wh,   g_wh);
    cudaGetSymbolAddress((void**)&bqkv, g_bqkv);

    cudaFuncSetAttribute(gemm_mma<true, __half>,  cudaFuncAttributeMaxDynamicSharedMemorySize, GEMM_SMEM);
    cudaFuncSetAttribute(gemm_mma<false, __half>, cudaFuncAttributeMaxDynamicSharedMemorySize, GEMM_SMEM);
    cudaFuncSetAttribute(gemm_mma<false, float>,  cudaFuncAttributeMaxDynamicSharedMemorySize, GEMM_SMEM);

    // 0) round operands to fp16: x and all weights; Wq|Wk|Wv contiguous.
    round_h_kernel<<<(TOK * Dm / 4 + 255) / 256, 256>>>(x, xh, TOK * Dm / 4);
    round_h_kernel<<<128, 256>>>(Wq, wh + OWQ,          32768);
    round_h_kernel<<<128, 256>>>(Wk, wh + OWQ + 131072, 32768);
    round_h_kernel<<<128, 256>>>(Wv, wh + OWQ + 262144, 32768);
    round_h_kernel<<<128, 256>>>(aW, wh + OAW,          32768);
    round_h_kernel<<<256, 256>>>(fW, wh + OFW,          65536);
    round_h_kernel<<<512, 256>>>(dW, wh + ODW,          131072);
    concat_bias_kernel<<<3, 256>>>(bq, bk, bv, bqkv);

    // 1) fused QKV projection on shifted x: [TOK,768] half
    gemm_mma<true, __half><<<dim3(QKV / 128, TOK / 128), 256, GEMM_SMEM>>>(
        xh, wh + OWQ, bqkv, qkv, TOK, QKV, Dm);

    // 2) windowed attention -> z (half)
    attn_kernel<<<TOK / 4, 128>>>(qkv, z);

    // 3) th = z @ aW^T + ab   (half out)
    gemm_mma<false, __half><<<dim3(Dm / 128, TOK / 128), 256, GEMM_SMEM>>>(
        z, wh + OAW, ab, th, TOK, Dm, HA);

    // 4) z2 = relu(x + unshift(LN(th)))  (half only)
    ln_shift_res_kernel<<<TOK, 128>>>(th, x, ag, abeta, z2h);

    // 5) th = z2 @ fW^T + fb  (half out)
    gemm_mma<false, __half><<<dim3(Dm / 128, TOK / 128), 256, GEMM_SMEM>>>(
        z2h, wh + OFW, fb, th, TOK, Dm, Dm);

    // 6) o1 = relu(z2 + LN(th))  (half residual, half out)
    ln_res_kernel<<<TOK, 128>>>(th, z2h, fg, fbeta, o1);

    // 7) patch merge = free reinterpret: o1 as [32768,1024]; t = merged @ dW^T + db (fp32 out)
    gemm_mma<false, float><<<dim3(Dm / 128, TOK / 2 / 128), 256, GEMM_SMEM>>>(
        o1, wh + ODW, db, t, TOK / 2, Dm, 2 * Dm);

    // 8) out = relu(LN(t))
    ln_final_kernel<<<TOK / 2, 128>>>(t, dg, dbeta, (float*)d_out);
}